// round 14
// baseline (speedup 1.0000x reference)
#include <cuda_runtime.h>
#include <cuda_bf16.h>
#include <cuda_fp16.h>
#include <mma.h>
#include <math_constants.h>

using namespace nvcuda;

#define NN 20000
#define EE 400000
#define TT 8
#define CINC 8
#define HID 16
#define HEADS 4
#define FF 128      // HID*TT
#define HF 512      // HEADS*HID*TT
#define SB 160      // stats blocks (hgat)
#define SNPB 125    // nodes per stats block
#define KB1 5000    // conv blocks (4 nodes each)

// ---------------- scratch (device globals) ----------------
__device__ float  g_h1[NN * FF];
__device__ float  g_res[NN * FF];
__device__ __half g_wh[FF * HF];              // fp16 gat_w (GEMM B)
__device__ __half g_linh[(size_t)NN * HF];    // fp16 GAT linear payload
__device__ float  g_as[NN * HEADS];
__device__ float  g_ad[NN * HEADS];
__device__ float  g_alpha[(size_t)EE * HEADS];
__device__ float  g_rsum[NN * HEADS];
__device__ float  g_hgat[NN * FF];
__device__ float  g_h2[NN * FF];
__device__ int    g_deg[NN];
__device__ int    g_off[NN + 1];
__device__ int    g_cur[NN];
__device__ int    g_srcsorted[EE];

__device__ float g_pcs1[KB1 * 16], g_pcq1[KB1 * 16];   // h1 per-block stat partials
__device__ float g_pcs2[KB1 * 16], g_pcq2[KB1 * 16];   // h2 per-block stat partials
__device__ double g_s2[FF], g_q2[FF];
__device__ float g_m1[HID], g_r1[HID];
__device__ float g_m2[FF],  g_r2[FF];
__device__ float g_m3[HID], g_r3[HID];

// ---------------- K0: zero scratch ----------------
__global__ void k0_zero() {
    int i = blockIdx.x * 256 + threadIdx.x;
    if (i < NN) { g_deg[i] = 0; g_cur[i] = 0; }
    if (i < FF) { g_s2[i] = 0.0; g_q2[i] = 0.0; }
}

// ---------------- K1: pointwise + residual + gated_conv1 + fused stats ----------------
// 128 threads = 4 nodes (1 warp each) x 16 o x 2 time-halves. grid = NN/4.
__global__ void __launch_bounds__(128) k1_front(
        const float* __restrict__ X,
        const float* __restrict__ w_in, const float* __restrict__ b_in,
        const float* __restrict__ res_w, const float* __restrict__ res_b,
        const float* __restrict__ w1, const float* __restrict__ b1,
        const float* __restrict__ w2, const float* __restrict__ b2,
        const float* __restrict__ w3, const float* __restrict__ b3) {
    __shared__ float s_winT[CINC * HID];
    __shared__ float s_rwT[HID * HID];
    __shared__ float s_w1T[HID * 3 * HID];
    __shared__ float s_w2T[HID * 3 * HID];
    __shared__ float s_w3T[HID * 3 * HID];
    __shared__ float s_bin[HID], s_rb[HID], s_b1[HID], s_b2[HID], s_b3[HID];
    __shared__ float s_x[4 * 168];
    __shared__ float s_sum[HID], s_sq[HID];

    int tid = threadIdx.x;
    for (int idx = tid; idx < HID * CINC; idx += 128) {
        int o = idx >> 3, c = idx & 7;
        s_winT[c * HID + o] = w_in[idx];
    }
    for (int idx = tid; idx < HID * HID; idx += 128) {
        int o = idx >> 4, i = idx & 15;
        s_rwT[i * HID + o] = res_w[idx];
    }
    for (int idx = tid; idx < HID * HID * 3; idx += 128) {
        int o = idx / 48, rest = idx % 48;
        s_w1T[rest * HID + o] = w1[idx];
        s_w2T[rest * HID + o] = w2[idx];
        s_w3T[rest * HID + o] = w3[idx];
    }
    if (tid < HID) {
        s_bin[tid] = b_in[tid]; s_rb[tid] = res_b[tid];
        s_b1[tid] = b1[tid]; s_b2[tid] = b2[tid]; s_b3[tid] = b3[tid];
        s_sum[tid] = 0.f; s_sq[tid] = 0.f;
    }
    __syncthreads();

    int nl = tid >> 5;            // warp = node
    int sub = tid & 31;
    int o = sub >> 1, th = sub & 1;
    int t0 = th * 4;
    int n = blockIdx.x * 4 + nl;  // NN = 5000*4
    float* xs = s_x + nl * 168;

    // ---- pointwise: x[o][t0..t0+3] ----
    {
        float acc[4];
        float bo = s_bin[o];
        #pragma unroll
        for (int t = 0; t < 4; t++) acc[t] = bo;
        const float* Xp = X + (size_t)n * CINC * TT;
        #pragma unroll
        for (int c = 0; c < CINC; c++) {
            float4 a = *(const float4*)&Xp[c * TT + t0];
            float w = s_winT[c * HID + o];
            acc[0] += a.x * w; acc[1] += a.y * w; acc[2] += a.z * w; acc[3] += a.w * w;
        }
        if (th == 0) xs[o * 10] = 0.f;
        #pragma unroll
        for (int t = 0; t < 4; t++) xs[o * 10 + 1 + t0 + t] = acc[t];
        if (th == 1) xs[o * 10 + 9] = 0.f;
    }
    __syncwarp();

    // ---- residual ----
    {
        float racc[4];
        float rbv = s_rb[o];
        #pragma unroll
        for (int t = 0; t < 4; t++) racc[t] = rbv;
        #pragma unroll
        for (int i = 0; i < HID; i++) {
            float w = s_rwT[i * HID + o];
            const float* xi = &xs[i * 10 + 1 + t0];
            #pragma unroll
            for (int t = 0; t < 4; t++) racc[t] += xi[t] * w;
        }
        *(float4*)&g_res[(size_t)n * FF + o * TT + t0] =
            make_float4(racc[0], racc[1], racc[2], racc[3]);
    }

    // ---- gated conv (4 t per thread) ----
    float p[4], q[4], r[4];
    {
        float b1v = s_b1[o], b2v = s_b2[o], b3v = s_b3[o];
        #pragma unroll
        for (int t = 0; t < 4; t++) { p[t] = b1v; q[t] = b2v; r[t] = b3v; }
    }
    #pragma unroll
    for (int i = 0; i < HID; i++) {
        float x6[6];
        #pragma unroll
        for (int u = 0; u < 6; u++) x6[u] = xs[i * 10 + t0 + u];
        float w10 = s_w1T[(i * 3 + 0) * HID + o];
        float w11 = s_w1T[(i * 3 + 1) * HID + o];
        float w12 = s_w1T[(i * 3 + 2) * HID + o];
        float w20 = s_w2T[(i * 3 + 0) * HID + o];
        float w21 = s_w2T[(i * 3 + 1) * HID + o];
        float w22 = s_w2T[(i * 3 + 2) * HID + o];
        float w30 = s_w3T[(i * 3 + 0) * HID + o];
        float w31 = s_w3T[(i * 3 + 1) * HID + o];
        float w32 = s_w3T[(i * 3 + 2) * HID + o];
        #pragma unroll
        for (int t = 0; t < 4; t++) {
            p[t] += w10 * x6[t] + w11 * x6[t + 1] + w12 * x6[t + 2];
            q[t] += w20 * x6[t] + w21 * x6[t + 1] + w22 * x6[t + 2];
            r[t] += w30 * x6[t] + w31 * x6[t + 1] + w32 * x6[t + 2];
        }
    }

    float hsum = 0.f, hsq = 0.f, hv[4];
    #pragma unroll
    for (int t = 0; t < 4; t++) {
        float sg = 1.f / (1.f + __expf(-q[t]));
        float h = p[t] * sg + r[t];
        h = h > 0.f ? h : 0.f;
        hv[t] = h; hsum += h; hsq += h * h;
    }
    *(float4*)&g_h1[(size_t)n * FF + o * TT + t0] =
        make_float4(hv[0], hv[1], hv[2], hv[3]);

    // stats: reduce th pair, then 16-address shared atomics (8 adds/address)
    hsum += __shfl_down_sync(0xffffffffu, hsum, 1, 2);
    hsq  += __shfl_down_sync(0xffffffffu, hsq, 1, 2);
    if (th == 0) { atomicAdd(&s_sum[o], hsum); atomicAdd(&s_sq[o], hsq); }
    __syncthreads();
    if (tid < HID) {
        g_pcs1[blockIdx.x * 16 + tid] = s_sum[tid];
        g_pcq1[blockIdx.x * 16 + tid] = s_sq[tid];
    }
}

// ---------------- per-feature stats over g_hgat ----------------
__global__ void __launch_bounds__(128) k_stats_f() {
    int t = threadIdx.x;
    int n0 = blockIdx.x * SNPB;
    float fs = 0.f, fq = 0.f;
    #pragma unroll 5
    for (int i = 0; i < SNPB; i++) {
        float v = g_hgat[(size_t)(n0 + i) * FF + t];
        fs += v; fq += v * v;
    }
    atomicAdd(&g_s2[t], (double)fs);
    atomicAdd(&g_q2[t], (double)fq);
}

// ---------------- finalize BN stats ----------------
// mode 0: reduce g_pcs1 -> m1/r1 ; mode 1: g_s2 -> m2/r2 ; mode 2: g_pcs2 -> m3/r3
__global__ void k_fin(int mode) {
    __shared__ float rs_[128], rq_[128];
    int tid = threadIdx.x;
    if (mode == 0 || mode == 2) {
        const float* P = (mode == 0) ? g_pcs1 : g_pcs2;
        const float* Q = (mode == 0) ? g_pcq1 : g_pcq2;
        int o = tid & 15, part = tid >> 4;   // 8 parts
        float s = 0.f, q = 0.f;
        for (int b = part; b < KB1; b += 8) {
            s += P[b * 16 + o];
            q += Q[b * 16 + o];
        }
        rs_[tid] = s; rq_[tid] = q;
        __syncthreads();
        if (tid < 16) {
            float a = 0.f, b2 = 0.f;
            #pragma unroll
            for (int pp = 0; pp < 8; pp++) { a += rs_[pp * 16 + tid]; b2 += rq_[pp * 16 + tid]; }
            double c = (double)NN * TT;
            double mu = (double)a / c;
            double va = (double)b2 / c - mu * mu;
            if (mode == 0) { g_m1[tid] = (float)mu; g_r1[tid] = (float)rsqrt(va + 1e-5); }
            else           { g_m3[tid] = (float)mu; g_r3[tid] = (float)rsqrt(va + 1e-5); }
        }
    } else {
        if (tid < FF) {
            double c = (double)NN;
            double mu = g_s2[tid] / c;
            double va = g_q2[tid] / c - mu * mu;
            g_m2[tid] = (float)mu; g_r2[tid] = (float)rsqrt(va + 1e-5);
        }
    }
}

// ---------------- K2pre_w: fp16 conversion of gat_w only ----------------
__global__ void __launch_bounds__(256) k2pre_w(const float* __restrict__ Wg) {
    int tid = blockIdx.x * 256 + threadIdx.x;
    if (tid < (FF * HF) / 8) {
        float4 w0 = *(const float4*)&Wg[tid * 8];
        float4 w1 = *(const float4*)&Wg[tid * 8 + 4];
        union { uint4 u; __half2 h[4]; } pw;
        pw.h[0] = __floats2half2_rn(w0.x, w0.y);
        pw.h[1] = __floats2half2_rn(w0.z, w0.w);
        pw.h[2] = __floats2half2_rn(w1.x, w1.y);
        pw.h[3] = __floats2half2_rn(w1.z, w1.w);
        *(uint4*)&g_wh[tid * 8] = pw.u;
    }
}

// ---------------- K2: WMMA tensor-core GEMM, A normalized+converted on load ----------------
__global__ void __launch_bounds__(256) k2_gemm(const float* __restrict__ att_s,
                                               const float* __restrict__ att_d) {
    __shared__ __align__(32) __half As[128][40];
    __shared__ __align__(32) __half Bs[32][136];
    __shared__ __align__(32) float Cst[8][256];
    __shared__ float sps[128], spd[128];
    __shared__ float sm1[HID], sr1[HID];

    int tid = threadIdx.x;
    int head = blockIdx.x, cb = head * 128;
    int nb = blockIdx.y * 128;
    int warp = tid >> 5, lane = tid & 31;
    int wm = warp & 3, wn = warp >> 2;

    if (tid < 128) { sps[tid] = 0.f; spd[tid] = 0.f; }
    if (tid < HID) { sm1[tid] = g_m1[tid]; sr1[tid] = g_r1[tid]; }
    __syncthreads();

    wmma::fragment<wmma::accumulator, 16, 16, 16, float> acc[2][4];
    #pragma unroll
    for (int mi = 0; mi < 2; mi++)
        #pragma unroll
        for (int ni = 0; ni < 4; ni++)
            wmma::fill_fragment(acc[mi][ni], 0.f);

    for (int kb = 0; kb < FF; kb += 32) {
        #pragma unroll
        for (int i = 0; i < 2; i++) {
            int id = tid * 2 + i;
            int row = id >> 2, seg = id & 3;
            int n = nb + row;
            int k0 = kb + seg * 8;
            int ch = k0 >> 3;
            float mu = sm1[ch], rs = sr1[ch];
            union { uint4 u; __half2 h[4]; } pk;
            if (n < NN) {
                float4 v0 = *(const float4*)&g_h1[(size_t)n * FF + k0];
                float4 v1 = *(const float4*)&g_h1[(size_t)n * FF + k0 + 4];
                pk.h[0] = __floats2half2_rn((v0.x - mu) * rs, (v0.y - mu) * rs);
                pk.h[1] = __floats2half2_rn((v0.z - mu) * rs, (v0.w - mu) * rs);
                pk.h[2] = __floats2half2_rn((v1.x - mu) * rs, (v1.y - mu) * rs);
                pk.h[3] = __floats2half2_rn((v1.z - mu) * rs, (v1.w - mu) * rs);
            } else {
                pk.u = make_uint4(0u, 0u, 0u, 0u);
            }
            *(uint4*)&As[row][seg * 8] = pk.u;
        }
        #pragma unroll
        for (int i = 0; i < 2; i++) {
            int id = tid * 2 + i;
            int row = id >> 4, seg = id & 15;
            *(uint4*)&Bs[row][seg * 8] = *(const uint4*)&g_wh[(size_t)(kb + row) * HF + cb + seg * 8];
        }
        __syncthreads();

        #pragma unroll
        for (int k16 = 0; k16 < 32; k16 += 16) {
            wmma::fragment<wmma::matrix_a, 16, 16, 16, __half, wmma::row_major> af[2];
            wmma::fragment<wmma::matrix_b, 16, 16, 16, __half, wmma::row_major> bf[4];
            #pragma unroll
            for (int mi = 0; mi < 2; mi++)
                wmma::load_matrix_sync(af[mi], &As[wm * 32 + mi * 16][k16], 40);
            #pragma unroll
            for (int ni = 0; ni < 4; ni++)
                wmma::load_matrix_sync(bf[ni], &Bs[k16][wn * 64 + ni * 16], 136);
            #pragma unroll
            for (int mi = 0; mi < 2; mi++)
                #pragma unroll
                for (int ni = 0; ni < 4; ni++)
                    wmma::mma_sync(acc[mi][ni], af[mi], bf[ni], acc[mi][ni]);
        }
        __syncthreads();
    }

    int r = lane & 15, hh = lane >> 4;
    #pragma unroll
    for (int mi = 0; mi < 2; mi++) {
        #pragma unroll
        for (int ni = 0; ni < 4; ni++) {
            wmma::store_matrix_sync(&Cst[warp][0], acc[mi][ni], 16, wmma::mem_row_major);
            __syncwarp();
            int m = wm * 32 + mi * 16 + r;
            int c0 = wn * 64 + ni * 16 + hh * 8;
            const float* cr = &Cst[warp][r * 16 + hh * 8];
            float ps = 0.f, pd = 0.f;
            #pragma unroll
            for (int j = 0; j < 8; j++) {
                ps += cr[j] * att_s[cb + c0 + j];
                pd += cr[j] * att_d[cb + c0 + j];
            }
            int n = nb + m;
            if (n < NN) {
                union { uint4 u; __half2 h[4]; } pk;
                pk.h[0] = __floats2half2_rn(cr[0], cr[1]);
                pk.h[1] = __floats2half2_rn(cr[2], cr[3]);
                pk.h[2] = __floats2half2_rn(cr[4], cr[5]);
                pk.h[3] = __floats2half2_rn(cr[6], cr[7]);
                *(uint4*)&g_linh[(size_t)n * HF + cb + c0] = pk.u;
            }
            atomicAdd(&sps[m], ps);
            atomicAdd(&spd[m], pd);
            __syncwarp();
        }
    }
    __syncthreads();
    if (tid < 128 && nb + tid < NN) {
        g_as[(nb + tid) * HEADS + head] = sps[tid];
        g_ad[(nb + tid) * HEADS + head] = spd[tid];
    }
}

// ---------------- K3: CSR build ----------------
__global__ void k3a_hist(const int* __restrict__ ei) {
    int e = blockIdx.x * 256 + threadIdx.x;
    if (e < EE) atomicAdd(&g_deg[ei[EE + e]], 1);
}

__global__ void k3b_scan() {
    int tid = threadIdx.x, lane = tid & 31, wid = tid >> 5;
    const int chunk = (NN + 1023) / 1024;
    int start = tid * chunk;
    int end = min(start + chunk, NN);
    int s = 0;
    for (int i = start; i < end; i++) s += g_deg[i];
    int v = s;
    #pragma unroll
    for (int off = 1; off < 32; off <<= 1) {
        int t = __shfl_up_sync(0xffffffffu, v, off);
        if (lane >= off) v += t;
    }
    __shared__ int wsum[32];
    if (lane == 31) wsum[wid] = v;
    __syncthreads();
    if (wid == 0) {
        int wv = wsum[lane];
        #pragma unroll
        for (int off = 1; off < 32; off <<= 1) {
            int t = __shfl_up_sync(0xffffffffu, wv, off);
            if (lane >= off) wv += t;
        }
        wsum[lane] = wv;
    }
    __syncthreads();
    int excl = v - s + (wid ? wsum[wid - 1] : 0);
    int run = excl;
    for (int i = start; i < end; i++) { g_off[i] = run; run += g_deg[i]; }
    if (tid == 1023) g_off[NN] = run;
}

__global__ void k3c_scatter(const int* __restrict__ ei) {
    int e = blockIdx.x * 256 + threadIdx.x;
    if (e < EE) {
        int d = ei[EE + e];
        int slot = g_off[d] + atomicAdd(&g_cur[d], 1);
        g_srcsorted[slot] = ei[e];
    }
}

// ---------------- K4a: per-dst softmax weights (warp per dst) ----------------
__global__ void __launch_bounds__(256) k4a_alpha() {
    int gw = (blockIdx.x * 256 + threadIdx.x) >> 5;
    if (gw >= NN) return;
    int lane = threadIdx.x & 31;
    int n = gw;
    int beg = g_off[n], end = g_off[n + 1];

    float4 ad4 = *(const float4*)&g_ad[n * HEADS];

    float4 mx = make_float4(-3.4e38f, -3.4e38f, -3.4e38f, -3.4e38f);
    for (int i = beg + lane; i < end; i += 32) {
        int s = g_srcsorted[i];
        float4 as4 = *(const float4*)&g_as[s * HEADS];
        float e0 = as4.x + ad4.x; e0 = e0 > 0.f ? e0 : 0.2f * e0;
        float e1 = as4.y + ad4.y; e1 = e1 > 0.f ? e1 : 0.2f * e1;
        float e2 = as4.z + ad4.z; e2 = e2 > 0.f ? e2 : 0.2f * e2;
        float e3 = as4.w + ad4.w; e3 = e3 > 0.f ? e3 : 0.2f * e3;
        mx.x = fmaxf(mx.x, e0); mx.y = fmaxf(mx.y, e1);
        mx.z = fmaxf(mx.z, e2); mx.w = fmaxf(mx.w, e3);
    }
    #pragma unroll
    for (int off = 16; off; off >>= 1) {
        mx.x = fmaxf(mx.x, __shfl_xor_sync(0xffffffffu, mx.x, off));
        mx.y = fmaxf(mx.y, __shfl_xor_sync(0xffffffffu, mx.y, off));
        mx.z = fmaxf(mx.z, __shfl_xor_sync(0xffffffffu, mx.z, off));
        mx.w = fmaxf(mx.w, __shfl_xor_sync(0xffffffffu, mx.w, off));
    }

    float4 sm = make_float4(0.f, 0.f, 0.f, 0.f);
    for (int i = beg + lane; i < end; i += 32) {
        int s = g_srcsorted[i];
        float4 as4 = *(const float4*)&g_as[s * HEADS];
        float e0 = as4.x + ad4.x; e0 = e0 > 0.f ? e0 : 0.2f * e0;
        float e1 = as4.y + ad4.y; e1 = e1 > 0.f ? e1 : 0.2f * e1;
        float e2 = as4.z + ad4.z; e2 = e2 > 0.f ? e2 : 0.2f * e2;
        float e3 = as4.w + ad4.w; e3 = e3 > 0.f ? e3 : 0.2f * e3;
        float4 ex = make_float4(__expf(e0 - mx.x), __expf(e1 - mx.y),
                                __expf(e2 - mx.z), __expf(e3 - mx.w));
        *(float4*)&g_alpha[(size_t)i * HEADS] = ex;
        sm.x += ex.x; sm.y += ex.y; sm.z += ex.z; sm.w += ex.w;
    }
    #pragma unroll
    for (int off = 16; off; off >>= 1) {
        sm.x += __shfl_xor_sync(0xffffffffu, sm.x, off);
        sm.y += __shfl_xor_sync(0xffffffffu, sm.y, off);
        sm.z += __shfl_xor_sync(0xffffffffu, sm.z, off);
        sm.w += __shfl_xor_sync(0xffffffffu, sm.w, off);
    }
    if (lane == 0) {
        *(float4*)&g_rsum[n * HEADS] =
            make_float4(1.f / (sm.x + 1e-16f), 1.f / (sm.y + 1e-16f),
                        1.f / (sm.z + 1e-16f), 1.f / (sm.w + 1e-16f));
    }
}

// ---------------- K4b: gather (block per dst) + head-mean ----------------
__global__ void __launch_bounds__(128) k4b_gather(const float* __restrict__ gat_b) {
    int n = blockIdx.x;
    int tid = threadIdx.x;  // 128
    int beg = g_off[n], end = g_off[n + 1];
    int hj = tid >> 5;

    __shared__ int sh_src[128];
    __shared__ __align__(16) float4 sh_al[128];
    __shared__ __align__(16) float s_out[HF];

    float4 racc = make_float4(0.f, 0.f, 0.f, 0.f);

    for (int base = beg; base < end; base += 128) {
        int i = base + tid;
        if (i < end) {
            sh_src[tid] = g_srcsorted[i];
            sh_al[tid] = *(const float4*)&g_alpha[(size_t)i * HEADS];
        }
        __syncthreads();
        int cnt = min(128, end - base);
        int j = 0;
        for (; j + 4 <= cnt; j += 4) {
            int s0 = sh_src[j], s1 = sh_src[j + 1], s2 = sh_src[j + 2], s3 = sh_src[j + 3];
            float a0 = ((const float*)&sh_al[j])[hj];
            float a1 = ((const float*)&sh_al[j + 1])[hj];
            float a2 = ((const float*)&sh_al[j + 2])[hj];
            float a3 = ((const float*)&sh_al[j + 3])[hj];
            uint2 r0 = *(const uint2*)&g_linh[(size_t)s0 * HF + tid * 4];
            uint2 r1 = *(const uint2*)&g_linh[(size_t)s1 * HF + tid * 4];
            uint2 r2 = *(const uint2*)&g_linh[(size_t)s2 * HF + tid * 4];
            uint2 r3 = *(const uint2*)&g_linh[(size_t)s3 * HF + tid * 4];
            float2 v0a = __half22float2(*(__half2*)&r0.x), v0b = __half22float2(*(__half2*)&r0.y);
            float2 v1a = __half22float2(*(__half2*)&r1.x), v1b = __half22float2(*(__half2*)&r1.y);
            float2 v2a = __half22float2(*(__half2*)&r2.x), v2b = __half22float2(*(__half2*)&r2.y);
            float2 v3a = __half22float2(*(__half2*)&r3.x), v3b = __half22float2(*(__half2*)&r3.y);
            racc.x += a0 * v0a.x + a1 * v1a.x + a2 * v2a.x + a3 * v3a.x;
            racc.y += a0 * v0a.y + a1 * v1a.y + a2 * v2a.y + a3 * v3a.y;
            racc.z += a0 * v0b.x + a1 * v1b.x + a2 * v2b.x + a3 * v3b.x;
            racc.w += a0 * v0b.y + a1 * v1b.y + a2 * v2b.y + a3 * v3b.y;
        }
        for (; j < cnt; j++) {
            int s = sh_src[j];
            float a = ((const float*)&sh_al[j])[hj];
            uint2 rr = *(const uint2*)&g_linh[(size_t)s * HF + tid * 4];
            float2 va = __half22float2(*(__half2*)&rr.x), vb = __half22float2(*(__half2*)&rr.y);
            racc.x += a * va.x; racc.y += a * va.y;
            racc.z += a * vb.x; racc.w += a * vb.y;
        }
        __syncthreads();
    }

    float rs = g_rsum[n * HEADS + hj];
    racc.x *= rs; racc.y *= rs; racc.z *= rs; racc.w *= rs;

    *(float4*)&s_out[tid * 4] = racc;
    __syncthreads();

    float v = 0.25f * (s_out[tid] + s_out[tid + FF] + s_out[tid + 2 * FF] + s_out[tid + 3 * FF])
              + gat_b[tid];
    g_hgat[(size_t)n * FF + tid] = v;
}

// ---------------- K5: bn2-normalize + gated_conv2 + fused stats ----------------
// same layout as k1: 4 nodes x 16 o x 2 th, grid NN/4
__global__ void __launch_bounds__(128) k5_conv2(
        const float* __restrict__ w1, const float* __restrict__ b1,
        const float* __restrict__ w2, const float* __restrict__ b2,
        const float* __restrict__ w3, const float* __restrict__ b3) {
    __shared__ float s_w1T[HID * 3 * HID], s_w2T[HID * 3 * HID], s_w3T[HID * 3 * HID];
    __shared__ float s_b1[HID], s_b2[HID], s_b3[HID];
    __shared__ float s_m2[FF], s_r2[FF];
    __shared__ float s_x[4 * 168];
    __shared__ float s_sum[HID], s_sq[HID];

    int tid = threadIdx.x;
    for (int idx = tid; idx < HID * HID * 3; idx += 128) {
        int o = idx / 48, rest = idx % 48;
        s_w1T[rest * HID + o] = w1[idx];
        s_w2T[rest * HID + o] = w2[idx];
        s_w3T[rest * HID + o] = w3[idx];
    }
    if (tid < HID) {
        s_b1[tid] = b1[tid]; s_b2[tid] = b2[tid]; s_b3[tid] = b3[tid];
        s_sum[tid] = 0.f; s_sq[tid] = 0.f;
    }
    if (tid < FF) { s_m2[tid] = g_m2[tid]; s_r2[tid] = g_r2[tid]; }
    __syncthreads();

    int nl = tid >> 5;
    int sub = tid & 31;
    int o = sub >> 1, th = sub & 1;
    int t0 = th * 4;
    int n = blockIdx.x * 4 + nl;
    float* xs = s_x + nl * 168;

    {
        float4 a = *(const float4*)&g_hgat[(size_t)n * FF + o * TT + t0];
        const float* m2 = &s_m2[o * TT + t0];
        const float* r2 = &s_r2[o * TT + t0];
        if (th == 0) xs[o * 10] = 0.f;
        xs[o * 10 + 1 + t0 + 0] = (a.x - m2[0]) * r2[0];
        xs[o * 10 + 1 + t0 + 1] = (a.y - m2[1]) * r2[1];
        xs[o * 10 + 1 + t0 + 2] = (a.z - m2[2]) * r2[2];
        xs[o * 10 + 1 + t0 + 3] = (a.w - m2[3]) * r2[3];
        if (th == 1) xs[o * 10 + 9] = 0.f;
    }
    __syncwarp();

    float p[4], q[4], r[4];
    {
        float b1v = s_b1[o], b2v = s_b2[o], b3v = s_b3[o];
        #pragma unroll
        for (int t = 0; t < 4; t++) { p[t] = b1v; q[t] = b2v; r[t] = b3v; }
    }
    #pragma unroll
    for (int i = 0; i < HID; i++) {
        float x6[6];
        #pragma unroll
        for (int u = 0; u < 6; u++) x6[u] = xs[i * 10 + t0 + u];
        float w10 = s_w1T[(i * 3 + 0) * HID + o];
        float w11 = s_w1T[(i * 3 + 1) * HID + o];
        float w12 = s_w1T[(i * 3 + 2) * HID + o];
        float w20 = s_w2T[(i * 3 + 0) * HID + o];
        float w21 = s_w2T[(i * 3 + 1) * HID + o];
        float w22 = s_w2T[(i * 3 + 2) * HID + o];
        float w30 = s_w3T[(i * 3 + 0) * HID + o];
        float w31 = s_w3T[(i * 3 + 1) * HID + o];
        float w32 = s_w3T[(i * 3 + 2) * HID + o];
        #pragma unroll
        for (int t = 0; t < 4; t++) {
            p[t] += w10 * x6[t] + w11 * x6[t + 1] + w12 * x6[t + 2];
            q[t] += w20 * x6[t] + w21 * x6[t + 1] + w22 * x6[t + 2];
            r[t] += w30 * x6[t] + w31 * x6[t + 1] + w32 * x6[t + 2];
        }
    }

    float hsum = 0.f, hsq = 0.f, hv[4];
    #pragma unroll
    for (int t = 0; t < 4; t++) {
        float sg = 1.f / (1.f + __expf(-q[t]));
        float h = p[t] * sg + r[t];
        h = h > 0.f ? h : 0.f;
        hv[t] = h; hsum += h; hsq += h * h;
    }
    *(float4*)&g_h2[(size_t)n * FF + o * TT + t0] =
        make_float4(hv[0], hv[1], hv[2], hv[3]);

    hsum += __shfl_down_sync(0xffffffffu, hsum, 1, 2);
    hsq  += __shfl_down_sync(0xffffffffu, hsq, 1, 2);
    if (th == 0) { atomicAdd(&s_sum[o], hsum); atomicAdd(&s_sq[o], hsq); }
    __syncthreads();
    if (tid < HID) {
        g_pcs2[blockIdx.x * 16 + tid] = s_sum[tid];
        g_pcq2[blockIdx.x * 16 + tid] = s_sq[tid];
    }
}

// ---------------- K6: epilogue ----------------
__global__ void k6_out(const float* __restrict__ ow1, const float* __restrict__ ob1,
                       const float* __restrict__ ow2, const float* __restrict__ ob2,
                       float* __restrict__ out) {
    int n = blockIdx.x;
    int tid = threadIdx.x;  // 64
    __shared__ float z[HID];
    __shared__ float ws[2];
    if (tid < HID) {
        size_t idx = (size_t)n * FF + tid * TT + (TT - 1);
        float h = (g_h2[idx] - g_m3[tid]) * g_r3[tid] + g_res[idx];
        z[tid] = h > 0.f ? h : 0.f;
    }
    __syncthreads();
    float y = ob1[tid];
    #pragma unroll
    for (int o = 0; o < HID; o++) y += z[o] * ow1[o * 64 + tid];
    y = y > 0.f ? y : 0.f;
    float contrib = y * ow2[tid];
    for (int off = 16; off; off >>= 1)
        contrib += __shfl_down_sync(0xffffffffu, contrib, off);
    if ((tid & 31) == 0) ws[tid >> 5] = contrib;
    __syncthreads();
    if (tid == 0) out[n] = ws[0] + ws[1] + ob2[0];
}

// ---------------- launch ----------------
extern "C" void kernel_launch(void* const* d_in, const int* in_sizes, int n_in,
                              void* d_out, int out_size) {
    const float* X       = (const float*)d_in[0];
    const int*   ei      = (const int*)  d_in[1];
    const float* w_in    = (const float*)d_in[2];
    const float* b_in    = (const float*)d_in[3];
    const float* res_w   = (const float*)d_in[4];
    const float* res_b   = (const float*)d_in[5];
    const float* tg1_w1  = (const float*)d_in[6];
    const float* tg1_b1  = (const float*)d_in[7];
    const float* tg1_w2  = (const float*)d_in[8];
    const float* tg1_b2  = (const float*)d_in[9];
    const float* tg1_w3  = (const float*)d_in[10];
    const float* tg1_b3  = (const float*)d_in[11];
    const float* gat_w   = (const float*)d_in[12];
    const float* att_src = (const float*)d_in[13];
    const float* att_dst = (const float*)d_in[14];
    const float* gat_b   = (const float*)d_in[15];
    const float* tg2_w1  = (const float*)d_in[16];
    const float* tg2_b1  = (const float*)d_in[17];
    const float* tg2_w2  = (const float*)d_in[18];
    const float* tg2_b2  = (const float*)d_in[19];
    const float* tg2_w3  = (const float*)d_in[20];
    const float* tg2_b3  = (const float*)d_in[21];
    const float* out_w1  = (const float*)d_in[22];
    const float* out_b1  = (const float*)d_in[23];
    const float* out_w2  = (const float*)d_in[24];
    const float* out_b2  = (const float*)d_in[25];
    float* out = (float*)d_out;

    k0_zero<<<(NN + 255) / 256, 256>>>();
    k3a_hist<<<(EE + 255) / 256, 256>>>(ei);
    k3b_scan<<<1, 1024>>>();
    k1_front<<<NN / 4, 128>>>(X, w_in, b_in, res_w, res_b,
                              tg1_w1, tg1_b1, tg1_w2, tg1_b2, tg1_w3, tg1_b3);
    k2pre_w<<<(FF * HF / 8 + 255) / 256, 256>>>(gat_w);
    k_fin<<<1, 128>>>(0);
    {
        dim3 grid(HEADS, (NN + 127) / 128);
        k2_gemm<<<grid, 256>>>(att_src, att_dst);
    }
    k3c_scatter<<<(EE + 255) / 256, 256>>>(ei);
    k4a_alpha<<<(NN * 32 + 255) / 256, 256>>>();
    k4b_gather<<<NN, 128>>>(gat_b);
    k_stats_f<<<SB, 128>>>();
    k_fin<<<1, 128>>>(1);
    k5_conv2<<<NN / 4, 128>>>(tg2_w1, tg2_b1, tg2_w2, tg2_b2, tg2_w3, tg2_b3);
    k_fin<<<1, 128>>>(2);
    k6_out<<<NN, 64>>>(out_w1, out_b1, out_w2, out_b2, out);
}

// round 15
// speedup vs baseline: 1.5107x; 1.5107x over previous
#include <cuda_runtime.h>
#include <cuda_bf16.h>
#include <cuda_fp16.h>
#include <mma.h>
#include <math_constants.h>

using namespace nvcuda;

#define NN 20000
#define EE 400000
#define TT 8
#define CINC 8
#define HID 16
#define HEADS 4
#define FF 128      // HID*TT
#define HF 512      // HEADS*HID*TT
#define NODE_ST 165
#define SB 160      // stats blocks
#define SNPB 125    // nodes per stats block

// ---------------- scratch (device globals) ----------------
__device__ float  g_h1[NN * FF];
__device__ float  g_res[NN * FF];
__device__ __half g_wh[FF * HF];              // fp16 gat_w (GEMM B)
__device__ __half g_linh[(size_t)NN * HF];    // fp16 GAT linear payload
__device__ float  g_as[NN * HEADS];
__device__ float  g_ad[NN * HEADS];
__device__ float  g_alpha[(size_t)EE * HEADS];
__device__ float  g_rsum[NN * HEADS];
__device__ float  g_hgat[NN * FF];
__device__ float  g_h2[NN * FF];
__device__ int    g_deg[NN];
__device__ int    g_off[NN + 1];
__device__ int    g_cur[NN];
__device__ int    g_srcsorted[EE];

__device__ double g_s1[HID], g_q1[HID];
__device__ double g_s2[FF],  g_q2[FF];
__device__ double g_s3[HID], g_q3[HID];
__device__ float g_m1[HID], g_r1[HID];
__device__ float g_m2[FF],  g_r2[FF];
__device__ float g_m3[HID], g_r3[HID];

// ---------------- K0: zero scratch ----------------
__global__ void k0_zero() {
    int i = blockIdx.x * 256 + threadIdx.x;
    if (i < NN) { g_deg[i] = 0; g_cur[i] = 0; }
    if (i < HID) { g_s1[i] = 0.0; g_q1[i] = 0.0; g_s3[i] = 0.0; g_q3[i] = 0.0; }
    if (i < FF)  { g_s2[i] = 0.0; g_q2[i] = 0.0; }
}

// ---------------- K1: pointwise + residual + gated_conv1 ----------------
__global__ void __launch_bounds__(128) k1_front(
        const float* __restrict__ X,
        const float* __restrict__ w_in, const float* __restrict__ b_in,
        const float* __restrict__ res_w, const float* __restrict__ res_b,
        const float* __restrict__ w1, const float* __restrict__ b1,
        const float* __restrict__ w2, const float* __restrict__ b2,
        const float* __restrict__ w3, const float* __restrict__ b3) {
    __shared__ float s_winT[CINC * HID];
    __shared__ float s_rwT[HID * HID];
    __shared__ float s_w1T[HID * 3 * HID];
    __shared__ float s_w2T[HID * 3 * HID];
    __shared__ float s_w3T[HID * 3 * HID];
    __shared__ float s_bin[HID], s_rb[HID], s_b1[HID], s_b2[HID], s_b3[HID];
    __shared__ float s_x[8 * NODE_ST];

    int tid = threadIdx.x;
    for (int idx = tid; idx < HID * CINC; idx += 128) {
        int o = idx >> 3, c = idx & 7;
        s_winT[c * HID + o] = w_in[idx];
    }
    for (int idx = tid; idx < HID * HID; idx += 128) {
        int o = idx >> 4, i = idx & 15;
        s_rwT[i * HID + o] = res_w[idx];
    }
    for (int idx = tid; idx < HID * HID * 3; idx += 128) {
        int o = idx / 48, rest = idx % 48;
        s_w1T[rest * HID + o] = w1[idx];
        s_w2T[rest * HID + o] = w2[idx];
        s_w3T[rest * HID + o] = w3[idx];
    }
    if (tid < HID) {
        s_bin[tid] = b_in[tid]; s_rb[tid] = res_b[tid];
        s_b1[tid] = b1[tid]; s_b2[tid] = b2[tid]; s_b3[tid] = b3[tid];
    }
    __syncthreads();

    int nl = tid >> 4, o = tid & 15;
    int n = blockIdx.x * 8 + nl;
    float* xs = s_x + nl * NODE_ST;

    float acc[TT];
    {
        float bo = s_bin[o];
        #pragma unroll
        for (int t = 0; t < TT; t++) acc[t] = bo;
        const float* Xp = X + (size_t)n * CINC * TT;
        #pragma unroll
        for (int c = 0; c < CINC; c++) {
            float4 a = *(const float4*)&Xp[c * TT];
            float4 b = *(const float4*)&Xp[c * TT + 4];
            float w = s_winT[c * HID + o];
            acc[0] += a.x * w; acc[1] += a.y * w; acc[2] += a.z * w; acc[3] += a.w * w;
            acc[4] += b.x * w; acc[5] += b.y * w; acc[6] += b.z * w; acc[7] += b.w * w;
        }
    }
    xs[o * 10] = 0.f;
    #pragma unroll
    for (int t = 0; t < TT; t++) xs[o * 10 + t + 1] = acc[t];
    xs[o * 10 + 9] = 0.f;
    __syncwarp();

    {
        float racc[TT];
        float rbv = s_rb[o];
        #pragma unroll
        for (int t = 0; t < TT; t++) racc[t] = rbv;
        #pragma unroll
        for (int i = 0; i < HID; i++) {
            float w = s_rwT[i * HID + o];
            const float* xi = &xs[i * 10 + 1];
            #pragma unroll
            for (int t = 0; t < TT; t++) racc[t] += xi[t] * w;
        }
        float* rp = &g_res[(size_t)n * FF + o * TT];
        *(float4*)rp       = make_float4(racc[0], racc[1], racc[2], racc[3]);
        *(float4*)(rp + 4) = make_float4(racc[4], racc[5], racc[6], racc[7]);
    }

    float p[TT], q[TT], r[TT];
    {
        float b1v = s_b1[o], b2v = s_b2[o], b3v = s_b3[o];
        #pragma unroll
        for (int t = 0; t < TT; t++) { p[t] = b1v; q[t] = b2v; r[t] = b3v; }
    }
    #pragma unroll
    for (int i = 0; i < HID; i++) {
        float x10[10];
        #pragma unroll
        for (int u = 0; u < 10; u++) x10[u] = xs[i * 10 + u];
        float w10 = s_w1T[(i * 3 + 0) * HID + o];
        float w11 = s_w1T[(i * 3 + 1) * HID + o];
        float w12 = s_w1T[(i * 3 + 2) * HID + o];
        float w20 = s_w2T[(i * 3 + 0) * HID + o];
        float w21 = s_w2T[(i * 3 + 1) * HID + o];
        float w22 = s_w2T[(i * 3 + 2) * HID + o];
        float w30 = s_w3T[(i * 3 + 0) * HID + o];
        float w31 = s_w3T[(i * 3 + 1) * HID + o];
        float w32 = s_w3T[(i * 3 + 2) * HID + o];
        #pragma unroll
        for (int t = 0; t < TT; t++) {
            p[t] += w10 * x10[t] + w11 * x10[t + 1] + w12 * x10[t + 2];
            q[t] += w20 * x10[t] + w21 * x10[t + 1] + w22 * x10[t + 2];
            r[t] += w30 * x10[t] + w31 * x10[t + 1] + w32 * x10[t + 2];
        }
    }

    float hv[TT];
    #pragma unroll
    for (int t = 0; t < TT; t++) {
        float sg = 1.f / (1.f + __expf(-q[t]));
        float h = p[t] * sg + r[t];
        hv[t] = h > 0.f ? h : 0.f;
    }
    float* hp = &g_h1[(size_t)n * FF + o * TT];
    *(float4*)hp       = make_float4(hv[0], hv[1], hv[2], hv[3]);
    *(float4*)(hp + 4) = make_float4(hv[4], hv[5], hv[6], hv[7]);
}

// ---------------- stats kernels (short atomic chains: SB per address) ----------------
__global__ void __launch_bounds__(128) k_stats_ch(int which) {
    const float* __restrict__ src = which ? g_h2 : g_h1;
    double* S = which ? g_s3 : g_s1;
    double* Q = which ? g_q3 : g_q1;
    int t = threadIdx.x;
    int n0 = blockIdx.x * SNPB;
    float fs = 0.f, fq = 0.f;
    #pragma unroll 5
    for (int i = 0; i < SNPB; i++) {
        float v = src[(size_t)(n0 + i) * FF + t];
        fs += v; fq += v * v;
    }
    __shared__ float ss[128], sq[128];
    ss[t] = fs; sq[t] = fq;
    __syncthreads();
    if (t < HID) {
        float a = 0.f, b = 0.f;
        #pragma unroll
        for (int j = 0; j < 8; j++) { a += ss[t * 8 + j]; b += sq[t * 8 + j]; }
        atomicAdd(&S[t], (double)a);
        atomicAdd(&Q[t], (double)b);
    }
}

__global__ void __launch_bounds__(128) k_stats_f() {
    int t = threadIdx.x;
    int n0 = blockIdx.x * SNPB;
    float fs = 0.f, fq = 0.f;
    #pragma unroll 5
    for (int i = 0; i < SNPB; i++) {
        float v = g_hgat[(size_t)(n0 + i) * FF + t];
        fs += v; fq += v * v;
    }
    atomicAdd(&g_s2[t], (double)fs);
    atomicAdd(&g_q2[t], (double)fq);
}

// ---------------- finalize BN stats ----------------
__global__ void k_fin(int mode) {
    int i = threadIdx.x;
    if (mode == 0 && i < HID) {
        double c = (double)NN * TT;
        double mu = g_s1[i] / c;
        double va = g_q1[i] / c - mu * mu;
        g_m1[i] = (float)mu; g_r1[i] = (float)rsqrt(va + 1e-5);
    }
    if (mode == 1 && i < FF) {
        double c = (double)NN;
        double mu = g_s2[i] / c;
        double va = g_q2[i] / c - mu * mu;
        g_m2[i] = (float)mu; g_r2[i] = (float)rsqrt(va + 1e-5);
    }
    if (mode == 2 && i < HID) {
        double c = (double)NN * TT;
        double mu = g_s3[i] / c;
        double va = g_q3[i] / c - mu * mu;
        g_m3[i] = (float)mu; g_r3[i] = (float)rsqrt(va + 1e-5);
    }
}

// ---------------- K2pre_w: fp16 conversion of gat_w only ----------------
__global__ void __launch_bounds__(256) k2pre_w(const float* __restrict__ Wg) {
    int tid = blockIdx.x * 256 + threadIdx.x;
    if (tid < (FF * HF) / 8) {
        float4 w0 = *(const float4*)&Wg[tid * 8];
        float4 w1 = *(const float4*)&Wg[tid * 8 + 4];
        union { uint4 u; __half2 h[4]; } pw;
        pw.h[0] = __floats2half2_rn(w0.x, w0.y);
        pw.h[1] = __floats2half2_rn(w0.z, w0.w);
        pw.h[2] = __floats2half2_rn(w1.x, w1.y);
        pw.h[3] = __floats2half2_rn(w1.z, w1.w);
        *(uint4*)&g_wh[tid * 8] = pw.u;
    }
}

// ---------------- K2: WMMA tensor-core GEMM, A normalized+converted on load ----------------
__global__ void __launch_bounds__(256) k2_gemm(const float* __restrict__ att_s,
                                               const float* __restrict__ att_d) {
    __shared__ __align__(32) __half As[128][40];
    __shared__ __align__(32) __half Bs[32][136];
    __shared__ __align__(32) float Cst[8][256];
    __shared__ float sps[128], spd[128];
    __shared__ float sm1[HID], sr1[HID];

    int tid = threadIdx.x;
    int head = blockIdx.x, cb = head * 128;
    int nb = blockIdx.y * 128;
    int warp = tid >> 5, lane = tid & 31;
    int wm = warp & 3, wn = warp >> 2;

    if (tid < 128) { sps[tid] = 0.f; spd[tid] = 0.f; }
    if (tid < HID) { sm1[tid] = g_m1[tid]; sr1[tid] = g_r1[tid]; }
    __syncthreads();

    wmma::fragment<wmma::accumulator, 16, 16, 16, float> acc[2][4];
    #pragma unroll
    for (int mi = 0; mi < 2; mi++)
        #pragma unroll
        for (int ni = 0; ni < 4; ni++)
            wmma::fill_fragment(acc[mi][ni], 0.f);

    for (int kb = 0; kb < FF; kb += 32) {
        #pragma unroll
        for (int i = 0; i < 2; i++) {
            int id = tid * 2 + i;
            int row = id >> 2, seg = id & 3;
            int n = nb + row;
            int k0 = kb + seg * 8;
            int ch = k0 >> 3;
            float mu = sm1[ch], rs = sr1[ch];
            union { uint4 u; __half2 h[4]; } pk;
            if (n < NN) {
                float4 v0 = *(const float4*)&g_h1[(size_t)n * FF + k0];
                float4 v1 = *(const float4*)&g_h1[(size_t)n * FF + k0 + 4];
                pk.h[0] = __floats2half2_rn((v0.x - mu) * rs, (v0.y - mu) * rs);
                pk.h[1] = __floats2half2_rn((v0.z - mu) * rs, (v0.w - mu) * rs);
                pk.h[2] = __floats2half2_rn((v1.x - mu) * rs, (v1.y - mu) * rs);
                pk.h[3] = __floats2half2_rn((v1.z - mu) * rs, (v1.w - mu) * rs);
            } else {
                pk.u = make_uint4(0u, 0u, 0u, 0u);
            }
            *(uint4*)&As[row][seg * 8] = pk.u;
        }
        #pragma unroll
        for (int i = 0; i < 2; i++) {
            int id = tid * 2 + i;
            int row = id >> 4, seg = id & 15;
            *(uint4*)&Bs[row][seg * 8] = *(const uint4*)&g_wh[(size_t)(kb + row) * HF + cb + seg * 8];
        }
        __syncthreads();

        #pragma unroll
        for (int k16 = 0; k16 < 32; k16 += 16) {
            wmma::fragment<wmma::matrix_a, 16, 16, 16, __half, wmma::row_major> af[2];
            wmma::fragment<wmma::matrix_b, 16, 16, 16, __half, wmma::row_major> bf[4];
            #pragma unroll
            for (int mi = 0; mi < 2; mi++)
                wmma::load_matrix_sync(af[mi], &As[wm * 32 + mi * 16][k16], 40);
            #pragma unroll
            for (int ni = 0; ni < 4; ni++)
                wmma::load_matrix_sync(bf[ni], &Bs[k16][wn * 64 + ni * 16], 136);
            #pragma unroll
            for (int mi = 0; mi < 2; mi++)
                #pragma unroll
                for (int ni = 0; ni < 4; ni++)
                    wmma::mma_sync(acc[mi][ni], af[mi], bf[ni], acc[mi][ni]);
        }
        __syncthreads();
    }

    int r = lane & 15, hh = lane >> 4;
    #pragma unroll
    for (int mi = 0; mi < 2; mi++) {
        #pragma unroll
        for (int ni = 0; ni < 4; ni++) {
            wmma::store_matrix_sync(&Cst[warp][0], acc[mi][ni], 16, wmma::mem_row_major);
            __syncwarp();
            int m = wm * 32 + mi * 16 + r;
            int c0 = wn * 64 + ni * 16 + hh * 8;
            const float* cr = &Cst[warp][r * 16 + hh * 8];
            float ps = 0.f, pd = 0.f;
            #pragma unroll
            for (int j = 0; j < 8; j++) {
                ps += cr[j] * att_s[cb + c0 + j];
                pd += cr[j] * att_d[cb + c0 + j];
            }
            int n = nb + m;
            if (n < NN) {
                union { uint4 u; __half2 h[4]; } pk;
                pk.h[0] = __floats2half2_rn(cr[0], cr[1]);
                pk.h[1] = __floats2half2_rn(cr[2], cr[3]);
                pk.h[2] = __floats2half2_rn(cr[4], cr[5]);
                pk.h[3] = __floats2half2_rn(cr[6], cr[7]);
                *(uint4*)&g_linh[(size_t)n * HF + cb + c0] = pk.u;
            }
            atomicAdd(&sps[m], ps);
            atomicAdd(&spd[m], pd);
            __syncwarp();
        }
    }
    __syncthreads();
    if (tid < 128 && nb + tid < NN) {
        g_as[(nb + tid) * HEADS + head] = sps[tid];
        g_ad[(nb + tid) * HEADS + head] = spd[tid];
    }
}

// ---------------- K3: CSR build ----------------
__global__ void k3a_hist(const int* __restrict__ ei) {
    int e = blockIdx.x * 256 + threadIdx.x;
    if (e < EE) atomicAdd(&g_deg[ei[EE + e]], 1);
}

__global__ void k3b_scan() {
    int tid = threadIdx.x, lane = tid & 31, wid = tid >> 5;
    const int chunk = (NN + 1023) / 1024;
    int start = tid * chunk;
    int end = min(start + chunk, NN);
    int s = 0;
    for (int i = start; i < end; i++) s += g_deg[i];
    int v = s;
    #pragma unroll
    for (int off = 1; off < 32; off <<= 1) {
        int t = __shfl_up_sync(0xffffffffu, v, off);
        if (lane >= off) v += t;
    }
    __shared__ int wsum[32];
    if (lane == 31) wsum[wid] = v;
    __syncthreads();
    if (wid == 0) {
        int wv = wsum[lane];
        #pragma unroll
        for (int off = 1; off < 32; off <<= 1) {
            int t = __shfl_up_sync(0xffffffffu, wv, off);
            if (lane >= off) wv += t;
        }
        wsum[lane] = wv;
    }
    __syncthreads();
    int excl = v - s + (wid ? wsum[wid - 1] : 0);
    int run = excl;
    for (int i = start; i < end; i++) { g_off[i] = run; run += g_deg[i]; }
    if (tid == 1023) g_off[NN] = run;
}

__global__ void k3c_scatter(const int* __restrict__ ei) {
    int e = blockIdx.x * 256 + threadIdx.x;
    if (e < EE) {
        int d = ei[EE + e];
        int slot = g_off[d] + atomicAdd(&g_cur[d], 1);
        g_srcsorted[slot] = ei[e];
    }
}

// ---------------- K4a: per-dst softmax weights (warp per dst) ----------------
__global__ void __launch_bounds__(256) k4a_alpha() {
    int gw = (blockIdx.x * 256 + threadIdx.x) >> 5;
    if (gw >= NN) return;
    int lane = threadIdx.x & 31;
    int n = gw;
    int beg = g_off[n], end = g_off[n + 1];

    float4 ad4 = *(const float4*)&g_ad[n * HEADS];

    float4 mx = make_float4(-3.4e38f, -3.4e38f, -3.4e38f, -3.4e38f);
    for (int i = beg + lane; i < end; i += 32) {
        int s = g_srcsorted[i];
        float4 as4 = *(const float4*)&g_as[s * HEADS];
        float e0 = as4.x + ad4.x; e0 = e0 > 0.f ? e0 : 0.2f * e0;
        float e1 = as4.y + ad4.y; e1 = e1 > 0.f ? e1 : 0.2f * e1;
        float e2 = as4.z + ad4.z; e2 = e2 > 0.f ? e2 : 0.2f * e2;
        float e3 = as4.w + ad4.w; e3 = e3 > 0.f ? e3 : 0.2f * e3;
        mx.x = fmaxf(mx.x, e0); mx.y = fmaxf(mx.y, e1);
        mx.z = fmaxf(mx.z, e2); mx.w = fmaxf(mx.w, e3);
    }
    #pragma unroll
    for (int off = 16; off; off >>= 1) {
        mx.x = fmaxf(mx.x, __shfl_xor_sync(0xffffffffu, mx.x, off));
        mx.y = fmaxf(mx.y, __shfl_xor_sync(0xffffffffu, mx.y, off));
        mx.z = fmaxf(mx.z, __shfl_xor_sync(0xffffffffu, mx.z, off));
        mx.w = fmaxf(mx.w, __shfl_xor_sync(0xffffffffu, mx.w, off));
    }

    float4 sm = make_float4(0.f, 0.f, 0.f, 0.f);
    for (int i = beg + lane; i < end; i += 32) {
        int s = g_srcsorted[i];
        float4 as4 = *(const float4*)&g_as[s * HEADS];
        float e0 = as4.x + ad4.x; e0 = e0 > 0.f ? e0 : 0.2f * e0;
        float e1 = as4.y + ad4.y; e1 = e1 > 0.f ? e1 : 0.2f * e1;
        float e2 = as4.z + ad4.z; e2 = e2 > 0.f ? e2 : 0.2f * e2;
        float e3 = as4.w + ad4.w; e3 = e3 > 0.f ? e3 : 0.2f * e3;
        float4 ex = make_float4(__expf(e0 - mx.x), __expf(e1 - mx.y),
                                __expf(e2 - mx.z), __expf(e3 - mx.w));
        *(float4*)&g_alpha[(size_t)i * HEADS] = ex;
        sm.x += ex.x; sm.y += ex.y; sm.z += ex.z; sm.w += ex.w;
    }
    #pragma unroll
    for (int off = 16; off; off >>= 1) {
        sm.x += __shfl_xor_sync(0xffffffffu, sm.x, off);
        sm.y += __shfl_xor_sync(0xffffffffu, sm.y, off);
        sm.z += __shfl_xor_sync(0xffffffffu, sm.z, off);
        sm.w += __shfl_xor_sync(0xffffffffu, sm.w, off);
    }
    if (lane == 0) {
        *(float4*)&g_rsum[n * HEADS] =
            make_float4(1.f / (sm.x + 1e-16f), 1.f / (sm.y + 1e-16f),
                        1.f / (sm.z + 1e-16f), 1.f / (sm.w + 1e-16f));
    }
}

// ---------------- K4b: gather (block per dst) + head-mean ----------------
__global__ void __launch_bounds__(128) k4b_gather(const float* __restrict__ gat_b) {
    int n = blockIdx.x;
    int tid = threadIdx.x;  // 128
    int beg = g_off[n], end = g_off[n + 1];
    int hj = tid >> 5;

    __shared__ int sh_src[128];
    __shared__ __align__(16) float4 sh_al[128];
    __shared__ __align__(16) float s_out[HF];

    float4 racc = make_float4(0.f, 0.f, 0.f, 0.f);

    for (int base = beg; base < end; base += 128) {
        int i = base + tid;
        if (i < end) {
            sh_src[tid] = g_srcsorted[i];
            sh_al[tid] = *(const float4*)&g_alpha[(size_t)i * HEADS];
        }
        __syncthreads();
        int cnt = min(128, end - base);
        int j = 0;
        for (; j + 4 <= cnt; j += 4) {
            int s0 = sh_src[j], s1 = sh_src[j + 1], s2 = sh_src[j + 2], s3 = sh_src[j + 3];
            float a0 = ((const float*)&sh_al[j])[hj];
            float a1 = ((const float*)&sh_al[j + 1])[hj];
            float a2 = ((const float*)&sh_al[j + 2])[hj];
            float a3 = ((const float*)&sh_al[j + 3])[hj];
            uint2 r0 = *(const uint2*)&g_linh[(size_t)s0 * HF + tid * 4];
            uint2 r1 = *(const uint2*)&g_linh[(size_t)s1 * HF + tid * 4];
            uint2 r2 = *(const uint2*)&g_linh[(size_t)s2 * HF + tid * 4];
            uint2 r3 = *(const uint2*)&g_linh[(size_t)s3 * HF + tid * 4];
            float2 v0a = __half22float2(*(__half2*)&r0.x), v0b = __half22float2(*(__half2*)&r0.y);
            float2 v1a = __half22float2(*(__half2*)&r1.x), v1b = __half22float2(*(__half2*)&r1.y);
            float2 v2a = __half22float2(*(__half2*)&r2.x), v2b = __half22float2(*(__half2*)&r2.y);
            float2 v3a = __half22float2(*(__half2*)&r3.x), v3b = __half22float2(*(__half2*)&r3.y);
            racc.x += a0 * v0a.x + a1 * v1a.x + a2 * v2a.x + a3 * v3a.x;
            racc.y += a0 * v0a.y + a1 * v1a.y + a2 * v2a.y + a3 * v3a.y;
            racc.z += a0 * v0b.x + a1 * v1b.x + a2 * v2b.x + a3 * v3b.x;
            racc.w += a0 * v0b.y + a1 * v1b.y + a2 * v2b.y + a3 * v3b.y;
        }
        for (; j < cnt; j++) {
            int s = sh_src[j];
            float a = ((const float*)&sh_al[j])[hj];
            uint2 rr = *(const uint2*)&g_linh[(size_t)s * HF + tid * 4];
            float2 va = __half22float2(*(__half2*)&rr.x), vb = __half22float2(*(__half2*)&rr.y);
            racc.x += a * va.x; racc.y += a * va.y;
            racc.z += a * vb.x; racc.w += a * vb.y;
        }
        __syncthreads();
    }

    float rs = g_rsum[n * HEADS + hj];
    racc.x *= rs; racc.y *= rs; racc.z *= rs; racc.w *= rs;

    *(float4*)&s_out[tid * 4] = racc;
    __syncthreads();

    float v = 0.25f * (s_out[tid] + s_out[tid + FF] + s_out[tid + 2 * FF] + s_out[tid + 3 * FF])
              + gat_b[tid];
    g_hgat[(size_t)n * FF + tid] = v;
}

// ---------------- K5: bn2-normalize + gated_conv2 ----------------
__global__ void __launch_bounds__(128) k5_conv2(
        const float* __restrict__ w1, const float* __restrict__ b1,
        const float* __restrict__ w2, const float* __restrict__ b2,
        const float* __restrict__ w3, const float* __restrict__ b3) {
    __shared__ float s_w1T[HID * 3 * HID], s_w2T[HID * 3 * HID], s_w3T[HID * 3 * HID];
    __shared__ float s_b1[HID], s_b2[HID], s_b3[HID];
    __shared__ float s_m2[FF], s_r2[FF];
    __shared__ float s_x[8 * NODE_ST];

    int tid = threadIdx.x;
    for (int idx = tid; idx < HID * HID * 3; idx += 128) {
        int o = idx / 48, rest = idx % 48;
        s_w1T[rest * HID + o] = w1[idx];
        s_w2T[rest * HID + o] = w2[idx];
        s_w3T[rest * HID + o] = w3[idx];
    }
    if (tid < HID) {
        s_b1[tid] = b1[tid]; s_b2[tid] = b2[tid]; s_b3[tid] = b3[tid];
    }
    if (tid < FF) { s_m2[tid] = g_m2[tid]; s_r2[tid] = g_r2[tid]; }
    __syncthreads();

    int nl = tid >> 4, o = tid & 15;
    int n = blockIdx.x * 8 + nl;
    float* xs = s_x + nl * NODE_ST;

    {
        const float* hp = &g_hgat[(size_t)n * FF + o * TT];
        float4 a = *(const float4*)hp;
        float4 b = *(const float4*)(hp + 4);
        const float* m2 = &s_m2[o * TT];
        const float* r2 = &s_r2[o * TT];
        xs[o * 10] = 0.f;
        xs[o * 10 + 1] = (a.x - m2[0]) * r2[0];
        xs[o * 10 + 2] = (a.y - m2[1]) * r2[1];
        xs[o * 10 + 3] = (a.z - m2[2]) * r2[2];
        xs[o * 10 + 4] = (a.w - m2[3]) * r2[3];
        xs[o * 10 + 5] = (b.x - m2[4]) * r2[4];
        xs[o * 10 + 6] = (b.y - m2[5]) * r2[5];
        xs[o * 10 + 7] = (b.z - m2[6]) * r2[6];
        xs[o * 10 + 8] = (b.w - m2[7]) * r2[7];
        xs[o * 10 + 9] = 0.f;
    }
    __syncwarp();

    float p[TT], q[TT], r[TT];
    {
        float b1v = s_b1[o], b2v = s_b2[o], b3v = s_b3[o];
        #pragma unroll
        for (int t = 0; t < TT; t++) { p[t] = b1v; q[t] = b2v; r[t] = b3v; }
    }
    #pragma unroll
    for (int i = 0; i < HID; i++) {
        float x10[10];
        #pragma unroll
        for (int u = 0; u < 10; u++) x10[u] = xs[i * 10 + u];
        float w10 = s_w1T[(i * 3 + 0) * HID + o];
        float w11 = s_w1T[(i * 3 + 1) * HID + o];
        float w12 = s_w1T[(i * 3 + 2) * HID + o];
        float w20 = s_w2T[(i * 3 + 0) * HID + o];
        float w21 = s_w2T[(i * 3 + 1) * HID + o];
        float w22 = s_w2T[(i * 3 + 2) * HID + o];
        float w30 = s_w3T[(i * 3 + 0) * HID + o];
        float w31 = s_w3T[(i * 3 + 1) * HID + o];
        float w32 = s_w3T[(i * 3 + 2) * HID + o];
        #pragma unroll
        for (int t = 0; t < TT; t++) {
            p[t] += w10 * x10[t] + w11 * x10[t + 1] + w12 * x10[t + 2];
            q[t] += w20 * x10[t] + w21 * x10[t + 1] + w22 * x10[t + 2];
            r[t] += w30 * x10[t] + w31 * x10[t + 1] + w32 * x10[t + 2];
        }
    }

    float hv[TT];
    #pragma unroll
    for (int t = 0; t < TT; t++) {
        float sg = 1.f / (1.f + __expf(-q[t]));
        float h = p[t] * sg + r[t];
        hv[t] = h > 0.f ? h : 0.f;
    }
    float* hp = &g_h2[(size_t)n * FF + o * TT];
    *(float4*)hp       = make_float4(hv[0], hv[1], hv[2], hv[3]);
    *(float4*)(hp + 4) = make_float4(hv[4], hv[5], hv[6], hv[7]);
}

// ---------------- K6: epilogue ----------------
__global__ void k6_out(const float* __restrict__ ow1, const float* __restrict__ ob1,
                       const float* __restrict__ ow2, const float* __restrict__ ob2,
                       float* __restrict__ out) {
    int n = blockIdx.x;
    int tid = threadIdx.x;  // 64
    __shared__ float z[HID];
    __shared__ float ws[2];
    if (tid < HID) {
        size_t idx = (size_t)n * FF + tid * TT + (TT - 1);
        float h = (g_h2[idx] - g_m3[tid]) * g_r3[tid] + g_res[idx];
        z[tid] = h > 0.f ? h : 0.f;
    }
    __syncthreads();
    float y = ob1[tid];
    #pragma unroll
    for (int o = 0; o < HID; o++) y += z[o] * ow1[o * 64 + tid];
    y = y > 0.f ? y : 0.f;
    float contrib = y * ow2[tid];
    for (int off = 16; off; off >>= 1)
        contrib += __shfl_down_sync(0xffffffffu, contrib, off);
    if ((tid & 31) == 0) ws[tid >> 5] = contrib;
    __syncthreads();
    if (tid == 0) out[n] = ws[0] + ws[1] + ob2[0];
}

// ---------------- launch ----------------
extern "C" void kernel_launch(void* const* d_in, const int* in_sizes, int n_in,
                              void* d_out, int out_size) {
    const float* X       = (const float*)d_in[0];
    const int*   ei      = (const int*)  d_in[1];
    const float* w_in    = (const float*)d_in[2];
    const float* b_in    = (const float*)d_in[3];
    const float* res_w   = (const float*)d_in[4];
    const float* res_b   = (const float*)d_in[5];
    const float* tg1_w1  = (const float*)d_in[6];
    const float* tg1_b1  = (const float*)d_in[7];
    const float* tg1_w2  = (const float*)d_in[8];
    const float* tg1_b2  = (const float*)d_in[9];
    const float* tg1_w3  = (const float*)d_in[10];
    const float* tg1_b3  = (const float*)d_in[11];
    const float* gat_w   = (const float*)d_in[12];
    const float* att_src = (const float*)d_in[13];
    const float* att_dst = (const float*)d_in[14];
    const float* gat_b   = (const float*)d_in[15];
    const float* tg2_w1  = (const float*)d_in[16];
    const float* tg2_b1  = (const float*)d_in[17];
    const float* tg2_w2  = (const float*)d_in[18];
    const float* tg2_b2  = (const float*)d_in[19];
    const float* tg2_w3  = (const float*)d_in[20];
    const float* tg2_b3  = (const float*)d_in[21];
    const float* out_w1  = (const float*)d_in[22];
    const float* out_b1  = (const float*)d_in[23];
    const float* out_w2  = (const float*)d_in[24];
    const float* out_b2  = (const float*)d_in[25];
    float* out = (float*)d_out;

    k0_zero<<<(NN + 255) / 256, 256>>>();
    k3a_hist<<<(EE + 255) / 256, 256>>>(ei);
    k3b_scan<<<1, 1024>>>();
    k1_front<<<NN / 8, 128>>>(X, w_in, b_in, res_w, res_b,
                              tg1_w1, tg1_b1, tg1_w2, tg1_b2, tg1_w3, tg1_b3);
    k2pre_w<<<(FF * HF / 8 + 255) / 256, 256>>>(gat_w);
    k_stats_ch<<<SB, 128>>>(0);
    k_fin<<<1, 128>>>(0);
    {
        dim3 grid(HEADS, (NN + 127) / 128);
        k2_gemm<<<grid, 256>>>(att_src, att_dst);
    }
    k3c_scatter<<<(EE + 255) / 256, 256>>>(ei);
    k4a_alpha<<<(NN * 32 + 255) / 256, 256>>>();
    k4b_gather<<<NN, 128>>>(gat_b);
    k_stats_f<<<SB, 128>>>();
    k_fin<<<1, 128>>>(1);
    k5_conv2<<<NN / 8, 128>>>(tg2_w1, tg2_b1, tg2_w2, tg2_b2, tg2_w3, tg2_b3);
    k_stats_ch<<<SB, 128>>>(1);
    k_fin<<<1, 128>>>(2);
    k6_out<<<NN, 64>>>(out_w1, out_b1, out_w2, out_b2, out);
}

// round 16
// speedup vs baseline: 1.5239x; 1.0087x over previous
#include <cuda_runtime.h>
#include <cuda_bf16.h>
#include <cuda_fp16.h>
#include <mma.h>
#include <math_constants.h>

using namespace nvcuda;

#define NN 20000
#define EE 400000
#define TT 8
#define CINC 8
#define HID 16
#define HEADS 4
#define FF 128      // HID*TT
#define HF 512      // HEADS*HID*TT
#define NODE_ST 165
#define SB 160      // stats blocks
#define SNPB 125    // nodes per stats block

// ---------------- scratch (device globals) ----------------
__device__ float  g_h1[NN * FF];
__device__ float  g_res[NN * FF];
__device__ __half g_wh[FF * HF];              // fp16 gat_w (GEMM B)
__device__ __half g_linh[(size_t)NN * HF];    // fp16 GAT linear payload
__device__ float  g_as[NN * HEADS];
__device__ float  g_ad[NN * HEADS];
__device__ float  g_alpha[(size_t)EE * HEADS];
__device__ float  g_rsum[NN * HEADS];
__device__ float  g_hgat[NN * FF];
__device__ float  g_h2[NN * FF];
__device__ int    g_deg[NN];
__device__ int    g_off[NN + 1];
__device__ int    g_cur[NN];
__device__ int    g_srcsorted[EE];

__device__ double g_s1[HID], g_q1[HID];
__device__ double g_s2[FF],  g_q2[FF];
__device__ double g_s3[HID], g_q3[HID];
__device__ float g_m1[HID], g_r1[HID];
__device__ float g_m2[FF],  g_r2[FF];
__device__ float g_m3[HID], g_r3[HID];

// ---------------- K0: zero scratch + fp16 W conversion (fused) ----------------
__global__ void k0_zero(const float* __restrict__ Wg) {
    int i = blockIdx.x * 256 + threadIdx.x;
    if (i < NN) { g_deg[i] = 0; g_cur[i] = 0; }
    if (i < HID) { g_s1[i] = 0.0; g_q1[i] = 0.0; g_s3[i] = 0.0; g_q3[i] = 0.0; }
    if (i < FF)  { g_s2[i] = 0.0; g_q2[i] = 0.0; }
    if (i < (FF * HF) / 8) {
        float4 w0 = *(const float4*)&Wg[i * 8];
        float4 w1 = *(const float4*)&Wg[i * 8 + 4];
        union { uint4 u; __half2 h[4]; } pw;
        pw.h[0] = __floats2half2_rn(w0.x, w0.y);
        pw.h[1] = __floats2half2_rn(w0.z, w0.w);
        pw.h[2] = __floats2half2_rn(w1.x, w1.y);
        pw.h[3] = __floats2half2_rn(w1.z, w1.w);
        *(uint4*)&g_wh[i * 8] = pw.u;
    }
}

// ---------------- K1: pointwise + residual + gated_conv1 ----------------
__global__ void __launch_bounds__(128) k1_front(
        const float* __restrict__ X,
        const float* __restrict__ w_in, const float* __restrict__ b_in,
        const float* __restrict__ res_w, const float* __restrict__ res_b,
        const float* __restrict__ w1, const float* __restrict__ b1,
        const float* __restrict__ w2, const float* __restrict__ b2,
        const float* __restrict__ w3, const float* __restrict__ b3) {
    __shared__ float s_winT[CINC * HID];
    __shared__ float s_rwT[HID * HID];
    __shared__ float s_w1T[HID * 3 * HID];
    __shared__ float s_w2T[HID * 3 * HID];
    __shared__ float s_w3T[HID * 3 * HID];
    __shared__ float s_bin[HID], s_rb[HID], s_b1[HID], s_b2[HID], s_b3[HID];
    __shared__ float s_x[8 * NODE_ST];

    int tid = threadIdx.x;
    for (int idx = tid; idx < HID * CINC; idx += 128) {
        int o = idx >> 3, c = idx & 7;
        s_winT[c * HID + o] = w_in[idx];
    }
    for (int idx = tid; idx < HID * HID; idx += 128) {
        int o = idx >> 4, i = idx & 15;
        s_rwT[i * HID + o] = res_w[idx];
    }
    for (int idx = tid; idx < HID * HID * 3; idx += 128) {
        int o = idx / 48, rest = idx % 48;
        s_w1T[rest * HID + o] = w1[idx];
        s_w2T[rest * HID + o] = w2[idx];
        s_w3T[rest * HID + o] = w3[idx];
    }
    if (tid < HID) {
        s_bin[tid] = b_in[tid]; s_rb[tid] = res_b[tid];
        s_b1[tid] = b1[tid]; s_b2[tid] = b2[tid]; s_b3[tid] = b3[tid];
    }
    __syncthreads();

    int nl = tid >> 4, o = tid & 15;
    int n = blockIdx.x * 8 + nl;
    float* xs = s_x + nl * NODE_ST;

    float acc[TT];
    {
        float bo = s_bin[o];
        #pragma unroll
        for (int t = 0; t < TT; t++) acc[t] = bo;
        const float* Xp = X + (size_t)n * CINC * TT;
        #pragma unroll
        for (int c = 0; c < CINC; c++) {
            float4 a = *(const float4*)&Xp[c * TT];
            float4 b = *(const float4*)&Xp[c * TT + 4];
            float w = s_winT[c * HID + o];
            acc[0] += a.x * w; acc[1] += a.y * w; acc[2] += a.z * w; acc[3] += a.w * w;
            acc[4] += b.x * w; acc[5] += b.y * w; acc[6] += b.z * w; acc[7] += b.w * w;
        }
    }
    xs[o * 10] = 0.f;
    #pragma unroll
    for (int t = 0; t < TT; t++) xs[o * 10 + t + 1] = acc[t];
    xs[o * 10 + 9] = 0.f;
    __syncwarp();

    {
        float racc[TT];
        float rbv = s_rb[o];
        #pragma unroll
        for (int t = 0; t < TT; t++) racc[t] = rbv;
        #pragma unroll
        for (int i = 0; i < HID; i++) {
            float w = s_rwT[i * HID + o];
            const float* xi = &xs[i * 10 + 1];
            #pragma unroll
            for (int t = 0; t < TT; t++) racc[t] += xi[t] * w;
        }
        float* rp = &g_res[(size_t)n * FF + o * TT];
        *(float4*)rp       = make_float4(racc[0], racc[1], racc[2], racc[3]);
        *(float4*)(rp + 4) = make_float4(racc[4], racc[5], racc[6], racc[7]);
    }

    float p[TT], q[TT], r[TT];
    {
        float b1v = s_b1[o], b2v = s_b2[o], b3v = s_b3[o];
        #pragma unroll
        for (int t = 0; t < TT; t++) { p[t] = b1v; q[t] = b2v; r[t] = b3v; }
    }
    #pragma unroll
    for (int i = 0; i < HID; i++) {
        float x10[10];
        #pragma unroll
        for (int u = 0; u < 10; u++) x10[u] = xs[i * 10 + u];
        float w10 = s_w1T[(i * 3 + 0) * HID + o];
        float w11 = s_w1T[(i * 3 + 1) * HID + o];
        float w12 = s_w1T[(i * 3 + 2) * HID + o];
        float w20 = s_w2T[(i * 3 + 0) * HID + o];
        float w21 = s_w2T[(i * 3 + 1) * HID + o];
        float w22 = s_w2T[(i * 3 + 2) * HID + o];
        float w30 = s_w3T[(i * 3 + 0) * HID + o];
        float w31 = s_w3T[(i * 3 + 1) * HID + o];
        float w32 = s_w3T[(i * 3 + 2) * HID + o];
        #pragma unroll
        for (int t = 0; t < TT; t++) {
            p[t] += w10 * x10[t] + w11 * x10[t + 1] + w12 * x10[t + 2];
            q[t] += w20 * x10[t] + w21 * x10[t + 1] + w22 * x10[t + 2];
            r[t] += w30 * x10[t] + w31 * x10[t + 1] + w32 * x10[t + 2];
        }
    }

    float hv[TT];
    #pragma unroll
    for (int t = 0; t < TT; t++) {
        float sg = 1.f / (1.f + __expf(-q[t]));
        float h = p[t] * sg + r[t];
        hv[t] = h > 0.f ? h : 0.f;
    }
    float* hp = &g_h1[(size_t)n * FF + o * TT];
    *(float4*)hp       = make_float4(hv[0], hv[1], hv[2], hv[3]);
    *(float4*)(hp + 4) = make_float4(hv[4], hv[5], hv[6], hv[7]);
}

// ---------------- stats kernels (short atomic chains: SB per address) ----------------
__global__ void __launch_bounds__(128) k_stats_ch(int which) {
    const float* __restrict__ src = which ? g_h2 : g_h1;
    double* S = which ? g_s3 : g_s1;
    double* Q = which ? g_q3 : g_q1;
    int t = threadIdx.x;
    int n0 = blockIdx.x * SNPB;
    float fs = 0.f, fq = 0.f;
    #pragma unroll 5
    for (int i = 0; i < SNPB; i++) {
        float v = src[(size_t)(n0 + i) * FF + t];
        fs += v; fq += v * v;
    }
    __shared__ float ss[128], sq[128];
    ss[t] = fs; sq[t] = fq;
    __syncthreads();
    if (t < HID) {
        float a = 0.f, b = 0.f;
        #pragma unroll
        for (int j = 0; j < 8; j++) { a += ss[t * 8 + j]; b += sq[t * 8 + j]; }
        atomicAdd(&S[t], (double)a);
        atomicAdd(&Q[t], (double)b);
    }
}

__global__ void __launch_bounds__(128) k_stats_f() {
    int t = threadIdx.x;
    int n0 = blockIdx.x * SNPB;
    float fs = 0.f, fq = 0.f;
    #pragma unroll 5
    for (int i = 0; i < SNPB; i++) {
        float v = g_hgat[(size_t)(n0 + i) * FF + t];
        fs += v; fq += v * v;
    }
    atomicAdd(&g_s2[t], (double)fs);
    atomicAdd(&g_q2[t], (double)fq);
}

// ---------------- finalize BN stats ----------------
__global__ void k_fin(int mode) {
    int i = threadIdx.x;
    if (mode == 0 && i < HID) {
        double c = (double)NN * TT;
        double mu = g_s1[i] / c;
        double va = g_q1[i] / c - mu * mu;
        g_m1[i] = (float)mu; g_r1[i] = (float)rsqrt(va + 1e-5);
    }
    if (mode == 1 && i < FF) {
        double c = (double)NN;
        double mu = g_s2[i] / c;
        double va = g_q2[i] / c - mu * mu;
        g_m2[i] = (float)mu; g_r2[i] = (float)rsqrt(va + 1e-5);
    }
    if (mode == 2 && i < HID) {
        double c = (double)NN * TT;
        double mu = g_s3[i] / c;
        double va = g_q3[i] / c - mu * mu;
        g_m3[i] = (float)mu; g_r3[i] = (float)rsqrt(va + 1e-5);
    }
}

// ---------------- K2: WMMA tensor-core GEMM, A normalized+converted on load ----------------
__global__ void __launch_bounds__(256) k2_gemm(const float* __restrict__ att_s,
                                               const float* __restrict__ att_d) {
    __shared__ __align__(32) __half As[128][40];
    __shared__ __align__(32) __half Bs[32][136];
    __shared__ __align__(32) float Cst[8][256];
    __shared__ float sps[128], spd[128];
    __shared__ float sm1[HID], sr1[HID];
    __shared__ float s_as[128], s_ad[128];

    int tid = threadIdx.x;
    int head = blockIdx.x, cb = head * 128;
    int nb = blockIdx.y * 128;
    int warp = tid >> 5, lane = tid & 31;
    int wm = warp & 3, wn = warp >> 2;

    if (tid < 128) {
        sps[tid] = 0.f; spd[tid] = 0.f;
        s_as[tid] = att_s[cb + tid];
        s_ad[tid] = att_d[cb + tid];
    }
    if (tid < HID) { sm1[tid] = g_m1[tid]; sr1[tid] = g_r1[tid]; }
    __syncthreads();

    wmma::fragment<wmma::accumulator, 16, 16, 16, float> acc[2][4];
    #pragma unroll
    for (int mi = 0; mi < 2; mi++)
        #pragma unroll
        for (int ni = 0; ni < 4; ni++)
            wmma::fill_fragment(acc[mi][ni], 0.f);

    for (int kb = 0; kb < FF; kb += 32) {
        #pragma unroll
        for (int i = 0; i < 2; i++) {
            int id = tid * 2 + i;
            int row = id >> 2, seg = id & 3;
            int n = nb + row;
            int k0 = kb + seg * 8;
            int ch = k0 >> 3;
            float mu = sm1[ch], rs = sr1[ch];
            union { uint4 u; __half2 h[4]; } pk;
            if (n < NN) {
                float4 v0 = *(const float4*)&g_h1[(size_t)n * FF + k0];
                float4 v1 = *(const float4*)&g_h1[(size_t)n * FF + k0 + 4];
                pk.h[0] = __floats2half2_rn((v0.x - mu) * rs, (v0.y - mu) * rs);
                pk.h[1] = __floats2half2_rn((v0.z - mu) * rs, (v0.w - mu) * rs);
                pk.h[2] = __floats2half2_rn((v1.x - mu) * rs, (v1.y - mu) * rs);
                pk.h[3] = __floats2half2_rn((v1.z - mu) * rs, (v1.w - mu) * rs);
            } else {
                pk.u = make_uint4(0u, 0u, 0u, 0u);
            }
            *(uint4*)&As[row][seg * 8] = pk.u;
        }
        #pragma unroll
        for (int i = 0; i < 2; i++) {
            int id = tid * 2 + i;
            int row = id >> 4, seg = id & 15;
            *(uint4*)&Bs[row][seg * 8] = *(const uint4*)&g_wh[(size_t)(kb + row) * HF + cb + seg * 8];
        }
        __syncthreads();

        #pragma unroll
        for (int k16 = 0; k16 < 32; k16 += 16) {
            wmma::fragment<wmma::matrix_a, 16, 16, 16, __half, wmma::row_major> af[2];
            wmma::fragment<wmma::matrix_b, 16, 16, 16, __half, wmma::row_major> bf[4];
            #pragma unroll
            for (int mi = 0; mi < 2; mi++)
                wmma::load_matrix_sync(af[mi], &As[wm * 32 + mi * 16][k16], 40);
            #pragma unroll
            for (int ni = 0; ni < 4; ni++)
                wmma::load_matrix_sync(bf[ni], &Bs[k16][wn * 64 + ni * 16], 136);
            #pragma unroll
            for (int mi = 0; mi < 2; mi++)
                #pragma unroll
                for (int ni = 0; ni < 4; ni++)
                    wmma::mma_sync(acc[mi][ni], af[mi], bf[ni], acc[mi][ni]);
        }
        __syncthreads();
    }

    int r = lane & 15, hh = lane >> 4;
    #pragma unroll
    for (int mi = 0; mi < 2; mi++) {
        #pragma unroll
        for (int ni = 0; ni < 4; ni++) {
            wmma::store_matrix_sync(&Cst[warp][0], acc[mi][ni], 16, wmma::mem_row_major);
            __syncwarp();
            int m = wm * 32 + mi * 16 + r;
            int c0 = wn * 64 + ni * 16 + hh * 8;
            const float* cr = &Cst[warp][r * 16 + hh * 8];
            float ps = 0.f, pd = 0.f;
            #pragma unroll
            for (int j = 0; j < 8; j++) {
                ps += cr[j] * s_as[c0 + j];
                pd += cr[j] * s_ad[c0 + j];
            }
            int n = nb + m;
            if (n < NN) {
                union { uint4 u; __half2 h[4]; } pk;
                pk.h[0] = __floats2half2_rn(cr[0], cr[1]);
                pk.h[1] = __floats2half2_rn(cr[2], cr[3]);
                pk.h[2] = __floats2half2_rn(cr[4], cr[5]);
                pk.h[3] = __floats2half2_rn(cr[6], cr[7]);
                *(uint4*)&g_linh[(size_t)n * HF + cb + c0] = pk.u;
            }
            atomicAdd(&sps[m], ps);
            atomicAdd(&spd[m], pd);
            __syncwarp();
        }
    }
    __syncthreads();
    if (tid < 128 && nb + tid < NN) {
        g_as[(nb + tid) * HEADS + head] = sps[tid];
        g_ad[(nb + tid) * HEADS + head] = spd[tid];
    }
}

// ---------------- K3: CSR build ----------------
__global__ void k3a_hist(const int* __restrict__ ei) {
    int e = blockIdx.x * 256 + threadIdx.x;
    if (e < EE) atomicAdd(&g_deg[ei[EE + e]], 1);
}

__global__ void k3b_scan() {
    int tid = threadIdx.x, lane = tid & 31, wid = tid >> 5;
    const int chunk = (NN + 1023) / 1024;
    int start = tid * chunk;
    int end = min(start + chunk, NN);
    int s = 0;
    for (int i = start; i < end; i++) s += g_deg[i];
    int v = s;
    #pragma unroll
    for (int off = 1; off < 32; off <<= 1) {
        int t = __shfl_up_sync(0xffffffffu, v, off);
        if (lane >= off) v += t;
    }
    __shared__ int wsum[32];
    if (lane == 31) wsum[wid] = v;
    __syncthreads();
    if (wid == 0) {
        int wv = wsum[lane];
        #pragma unroll
        for (int off = 1; off < 32; off <<= 1) {
            int t = __shfl_up_sync(0xffffffffu, wv, off);
            if (lane >= off) wv += t;
        }
        wsum[lane] = wv;
    }
    __syncthreads();
    int excl = v - s + (wid ? wsum[wid - 1] : 0);
    int run = excl;
    for (int i = start; i < end; i++) { g_off[i] = run; run += g_deg[i]; }
    if (tid == 1023) g_off[NN] = run;
}

__global__ void k3c_scatter(const int* __restrict__ ei) {
    int e = blockIdx.x * 256 + threadIdx.x;
    if (e < EE) {
        int d = ei[EE + e];
        int slot = g_off[d] + atomicAdd(&g_cur[d], 1);
        g_srcsorted[slot] = ei[e];
    }
}

// ---------------- K4a: per-dst softmax weights (warp per dst) ----------------
__global__ void __launch_bounds__(256) k4a_alpha() {
    int gw = (blockIdx.x * 256 + threadIdx.x) >> 5;
    if (gw >= NN) return;
    int lane = threadIdx.x & 31;
    int n = gw;
    int beg = g_off[n], end = g_off[n + 1];

    float4 ad4 = *(const float4*)&g_ad[n * HEADS];

    float4 mx = make_float4(-3.4e38f, -3.4e38f, -3.4e38f, -3.4e38f);
    for (int i = beg + lane; i < end; i += 32) {
        int s = g_srcsorted[i];
        float4 as4 = *(const float4*)&g_as[s * HEADS];
        float e0 = as4.x + ad4.x; e0 = e0 > 0.f ? e0 : 0.2f * e0;
        float e1 = as4.y + ad4.y; e1 = e1 > 0.f ? e1 : 0.2f * e1;
        float e2 = as4.z + ad4.z; e2 = e2 > 0.f ? e2 : 0.2f * e2;
        float e3 = as4.w + ad4.w; e3 = e3 > 0.f ? e3 : 0.2f * e3;
        mx.x = fmaxf(mx.x, e0); mx.y = fmaxf(mx.y, e1);
        mx.z = fmaxf(mx.z, e2); mx.w = fmaxf(mx.w, e3);
    }
    #pragma unroll
    for (int off = 16; off; off >>= 1) {
        mx.x = fmaxf(mx.x, __shfl_xor_sync(0xffffffffu, mx.x, off));
        mx.y = fmaxf(mx.y, __shfl_xor_sync(0xffffffffu, mx.y, off));
        mx.z = fmaxf(mx.z, __shfl_xor_sync(0xffffffffu, mx.z, off));
        mx.w = fmaxf(mx.w, __shfl_xor_sync(0xffffffffu, mx.w, off));
    }

    float4 sm = make_float4(0.f, 0.f, 0.f, 0.f);
    for (int i = beg + lane; i < end; i += 32) {
        int s = g_srcsorted[i];
        float4 as4 = *(const float4*)&g_as[s * HEADS];
        float e0 = as4.x + ad4.x; e0 = e0 > 0.f ? e0 : 0.2f * e0;
        float e1 = as4.y + ad4.y; e1 = e1 > 0.f ? e1 : 0.2f * e1;
        float e2 = as4.z + ad4.z; e2 = e2 > 0.f ? e2 : 0.2f * e2;
        float e3 = as4.w + ad4.w; e3 = e3 > 0.f ? e3 : 0.2f * e3;
        float4 ex = make_float4(__expf(e0 - mx.x), __expf(e1 - mx.y),
                                __expf(e2 - mx.z), __expf(e3 - mx.w));
        *(float4*)&g_alpha[(size_t)i * HEADS] = ex;
        sm.x += ex.x; sm.y += ex.y; sm.z += ex.z; sm.w += ex.w;
    }
    #pragma unroll
    for (int off = 16; off; off >>= 1) {
        sm.x += __shfl_xor_sync(0xffffffffu, sm.x, off);
        sm.y += __shfl_xor_sync(0xffffffffu, sm.y, off);
        sm.z += __shfl_xor_sync(0xffffffffu, sm.z, off);
        sm.w += __shfl_xor_sync(0xffffffffu, sm.w, off);
    }
    if (lane == 0) {
        *(float4*)&g_rsum[n * HEADS] =
            make_float4(1.f / (sm.x + 1e-16f), 1.f / (sm.y + 1e-16f),
                        1.f / (sm.z + 1e-16f), 1.f / (sm.w + 1e-16f));
    }
}

// ---------------- K4b: gather (block per dst) + head-mean ----------------
__global__ void __launch_bounds__(128) k4b_gather(const float* __restrict__ gat_b) {
    int n = blockIdx.x;
    int tid = threadIdx.x;  // 128
    int beg = g_off[n], end = g_off[n + 1];
    int hj = tid >> 5;

    __shared__ int sh_src[128];
    __shared__ __align__(16) float4 sh_al[128];
    __shared__ __align__(16) float s_out[HF];

    float4 racc = make_float4(0.f, 0.f, 0.f, 0.f);

    for (int base = beg; base < end; base += 128) {
        int i = base + tid;
        if (i < end) {
            sh_src[tid] = g_srcsorted[i];
            sh_al[tid] = *(const float4*)&g_alpha[(size_t)i * HEADS];
        }
        __syncthreads();
        int cnt = min(128, end - base);
        int j = 0;
        for (; j + 4 <= cnt; j += 4) {
            int s0 = sh_src[j], s1 = sh_src[j + 1], s2 = sh_src[j + 2], s3 = sh_src[j + 3];
            float a0 = ((const float*)&sh_al[j])[hj];
            float a1 = ((const float*)&sh_al[j + 1])[hj];
            float a2 = ((const float*)&sh_al[j + 2])[hj];
            float a3 = ((const float*)&sh_al[j + 3])[hj];
            uint2 r0 = *(const uint2*)&g_linh[(size_t)s0 * HF + tid * 4];
            uint2 r1 = *(const uint2*)&g_linh[(size_t)s1 * HF + tid * 4];
            uint2 r2 = *(const uint2*)&g_linh[(size_t)s2 * HF + tid * 4];
            uint2 r3 = *(const uint2*)&g_linh[(size_t)s3 * HF + tid * 4];
            float2 v0a = __half22float2(*(__half2*)&r0.x), v0b = __half22float2(*(__half2*)&r0.y);
            float2 v1a = __half22float2(*(__half2*)&r1.x), v1b = __half22float2(*(__half2*)&r1.y);
            float2 v2a = __half22float2(*(__half2*)&r2.x), v2b = __half22float2(*(__half2*)&r2.y);
            float2 v3a = __half22float2(*(__half2*)&r3.x), v3b = __half22float2(*(__half2*)&r3.y);
            racc.x += a0 * v0a.x + a1 * v1a.x + a2 * v2a.x + a3 * v3a.x;
            racc.y += a0 * v0a.y + a1 * v1a.y + a2 * v2a.y + a3 * v3a.y;
            racc.z += a0 * v0b.x + a1 * v1b.x + a2 * v2b.x + a3 * v3b.x;
            racc.w += a0 * v0b.y + a1 * v1b.y + a2 * v2b.y + a3 * v3b.y;
        }
        for (; j < cnt; j++) {
            int s = sh_src[j];
            float a = ((const float*)&sh_al[j])[hj];
            uint2 rr = *(const uint2*)&g_linh[(size_t)s * HF + tid * 4];
            float2 va = __half22float2(*(__half2*)&rr.x), vb = __half22float2(*(__half2*)&rr.y);
            racc.x += a * va.x; racc.y += a * va.y;
            racc.z += a * vb.x; racc.w += a * vb.y;
        }
        __syncthreads();
    }

    float rs = g_rsum[n * HEADS + hj];
    racc.x *= rs; racc.y *= rs; racc.z *= rs; racc.w *= rs;

    *(float4*)&s_out[tid * 4] = racc;
    __syncthreads();

    float v = 0.25f * (s_out[tid] + s_out[tid + FF] + s_out[tid + 2 * FF] + s_out[tid + 3 * FF])
              + gat_b[tid];
    g_hgat[(size_t)n * FF + tid] = v;
}

// ---------------- K5: bn2-normalize + gated_conv2 ----------------
__global__ void __launch_bounds__(128) k5_conv2(
        const float* __restrict__ w1, const float* __restrict__ b1,
        const float* __restrict__ w2, const float* __restrict__ b2,
        const float* __restrict__ w3, const float* __restrict__ b3) {
    __shared__ float s_w1T[HID * 3 * HID], s_w2T[HID * 3 * HID], s_w3T[HID * 3 * HID];
    __shared__ float s_b1[HID], s_b2[HID], s_b3[HID];
    __shared__ float s_m2[FF], s_r2[FF];
    __shared__ float s_x[8 * NODE_ST];

    int tid = threadIdx.x;
    for (int idx = tid; idx < HID * HID * 3; idx += 128) {
        int o = idx / 48, rest = idx % 48;
        s_w1T[rest * HID + o] = w1[idx];
        s_w2T[rest * HID + o] = w2[idx];
        s_w3T[rest * HID + o] = w3[idx];
    }
    if (tid < HID) {
        s_b1[tid] = b1[tid]; s_b2[tid] = b2[tid]; s_b3[tid] = b3[tid];
    }
    if (tid < FF) { s_m2[tid] = g_m2[tid]; s_r2[tid] = g_r2[tid]; }
    __syncthreads();

    int nl = tid >> 4, o = tid & 15;
    int n = blockIdx.x * 8 + nl;
    float* xs = s_x + nl * NODE_ST;

    {
        const float* hp = &g_hgat[(size_t)n * FF + o * TT];
        float4 a = *(const float4*)hp;
        float4 b = *(const float4*)(hp + 4);
        const float* m2 = &s_m2[o * TT];
        const float* r2 = &s_r2[o * TT];
        xs[o * 10] = 0.f;
        xs[o * 10 + 1] = (a.x - m2[0]) * r2[0];
        xs[o * 10 + 2] = (a.y - m2[1]) * r2[1];
        xs[o * 10 + 3] = (a.z - m2[2]) * r2[2];
        xs[o * 10 + 4] = (a.w - m2[3]) * r2[3];
        xs[o * 10 + 5] = (b.x - m2[4]) * r2[4];
        xs[o * 10 + 6] = (b.y - m2[5]) * r2[5];
        xs[o * 10 + 7] = (b.z - m2[6]) * r2[6];
        xs[o * 10 + 8] = (b.w - m2[7]) * r2[7];
        xs[o * 10 + 9] = 0.f;
    }
    __syncwarp();

    float p[TT], q[TT], r[TT];
    {
        float b1v = s_b1[o], b2v = s_b2[o], b3v = s_b3[o];
        #pragma unroll
        for (int t = 0; t < TT; t++) { p[t] = b1v; q[t] = b2v; r[t] = b3v; }
    }
    #pragma unroll
    for (int i = 0; i < HID; i++) {
        float x10[10];
        #pragma unroll
        for (int u = 0; u < 10; u++) x10[u] = xs[i * 10 + u];
        float w10 = s_w1T[(i * 3 + 0) * HID + o];
        float w11 = s_w1T[(i * 3 + 1) * HID + o];
        float w12 = s_w1T[(i * 3 + 2) * HID + o];
        float w20 = s_w2T[(i * 3 + 0) * HID + o];
        float w21 = s_w2T[(i * 3 + 1) * HID + o];
        float w22 = s_w2T[(i * 3 + 2) * HID + o];
        float w30 = s_w3T[(i * 3 + 0) * HID + o];
        float w31 = s_w3T[(i * 3 + 1) * HID + o];
        float w32 = s_w3T[(i * 3 + 2) * HID + o];
        #pragma unroll
        for (int t = 0; t < TT; t++) {
            p[t] += w10 * x10[t] + w11 * x10[t + 1] + w12 * x10[t + 2];
            q[t] += w20 * x10[t] + w21 * x10[t + 1] + w22 * x10[t + 2];
            r[t] += w30 * x10[t] + w31 * x10[t + 1] + w32 * x10[t + 2];
        }
    }

    float hv[TT];
    #pragma unroll
    for (int t = 0; t < TT; t++) {
        float sg = 1.f / (1.f + __expf(-q[t]));
        float h = p[t] * sg + r[t];
        hv[t] = h > 0.f ? h : 0.f;
    }
    float* hp = &g_h2[(size_t)n * FF + o * TT];
    *(float4*)hp       = make_float4(hv[0], hv[1], hv[2], hv[3]);
    *(float4*)(hp + 4) = make_float4(hv[4], hv[5], hv[6], hv[7]);
}

// ---------------- K6: epilogue ----------------
__global__ void k6_out(const float* __restrict__ ow1, const float* __restrict__ ob1,
                       const float* __restrict__ ow2, const float* __restrict__ ob2,
                       float* __restrict__ out) {
    int n = blockIdx.x;
    int tid = threadIdx.x;  // 64
    __shared__ float z[HID];
    __shared__ float ws[2];
    if (tid < HID) {
        size_t idx = (size_t)n * FF + tid * TT + (TT - 1);
        float h = (g_h2[idx] - g_m3[tid]) * g_r3[tid] + g_res[idx];
        z[tid] = h > 0.f ? h : 0.f;
    }
    __syncthreads();
    float y = ob1[tid];
    #pragma unroll
    for (int o = 0; o < HID; o++) y += z[o] * ow1[o * 64 + tid];
    y = y > 0.f ? y : 0.f;
    float contrib = y * ow2[tid];
    for (int off = 16; off; off >>= 1)
        contrib += __shfl_down_sync(0xffffffffu, contrib, off);
    if ((tid & 31) == 0) ws[tid >> 5] = contrib;
    __syncthreads();
    if (tid == 0) out[n] = ws[0] + ws[1] + ob2[0];
}

// ---------------- launch ----------------
extern "C" void kernel_launch(void* const* d_in, const int* in_sizes, int n_in,
                              void* d_out, int out_size) {
    const float* X       = (const float*)d_in[0];
    const int*   ei      = (const int*)  d_in[1];
    const float* w_in    = (const float*)d_in[2];
    const float* b_in    = (const float*)d_in[3];
    const float* res_w   = (const float*)d_in[4];
    const float* res_b   = (const float*)d_in[5];
    const float* tg1_w1  = (const float*)d_in[6];
    const float* tg1_b1  = (const float*)d_in[7];
    const float* tg1_w2  = (const float*)d_in[8];
    const float* tg1_b2  = (const float*)d_in[9];
    const float* tg1_w3  = (const float*)d_in[10];
    const float* tg1_b3  = (const float*)d_in[11];
    const float* gat_w   = (const float*)d_in[12];
    const float* att_src = (const float*)d_in[13];
    const float* att_dst = (const float*)d_in[14];
    const float* gat_b   = (const float*)d_in[15];
    const float* tg2_w1  = (const float*)d_in[16];
    const float* tg2_b1  = (const float*)d_in[17];
    const float* tg2_w2  = (const float*)d_in[18];
    const float* tg2_b2  = (const float*)d_in[19];
    const float* tg2_w3  = (const float*)d_in[20];
    const float* tg2_b3  = (const float*)d_in[21];
    const float* out_w1  = (const float*)d_in[22];
    const float* out_b1  = (const float*)d_in[23];
    const float* out_w2  = (const float*)d_in[24];
    const float* out_b2  = (const float*)d_in[25];
    float* out = (float*)d_out;

    k0_zero<<<(NN + 255) / 256, 256>>>(gat_w);
    k3a_hist<<<(EE + 255) / 256, 256>>>(ei);
    k3b_scan<<<1, 1024>>>();
    k1_front<<<NN / 8, 128>>>(X, w_in, b_in, res_w, res_b,
                              tg1_w1, tg1_b1, tg1_w2, tg1_b2, tg1_w3, tg1_b3);
    k_stats_ch<<<SB, 128>>>(0);
    k_fin<<<1, 128>>>(0);
    {
        dim3 grid(HEADS, (NN + 127) / 128);
        k2_gemm<<<grid, 256>>>(att_src, att_dst);
    }
    k3c_scatter<<<(EE + 255) / 256, 256>>>(ei);
    k4a_alpha<<<(NN * 32 + 255) / 256, 256>>>();
    k4b_gather<<<NN, 128>>>(gat_b);
    k_stats_f<<<SB, 128>>>();
    k_fin<<<1, 128>>>(1);
    k5_conv2<<<NN / 8, 128>>>(tg2_w1, tg2_b1, tg2_w2, tg2_b2, tg2_w3, tg2_b3);
    k_stats_ch<<<SB, 128>>>(1);
    k_fin<<<1, 128>>>(2);
    k6_out<<<NN, 64>>>(out_w1, out_b1, out_w2, out_b2, out);
}